// round 14
// baseline (speedup 1.0000x reference)
#include <cuda_runtime.h>
#include <cuda_bf16.h>
#include <cuda_fp8.h>
#include <math.h>

#define B_SZ 2
#define SEQ  1024
#define DM   1024
#define DI   2048
#define DS   16
#define DFF  4096
#define MTOK (B_SZ*SEQ)

// ---- bf16 GEMM tiling: CTA 128x256, 512 thr (4x4 warps), BK=32, 3-stage ----
#define BM 128
#define BN 256
#define BK 32
#define NSTAGE 3
#define ROWB 80
#define A_SPLIT (BM*ROWB)
#define A_BOTH  (2*A_SPLIT)
#define B_SPLIT (BN*ROWB)
#define B_BOTH  (2*B_SPLIT)
#define STAGE_B (A_BOTH + B_BOTH)
#define SMEM_B  (NSTAGE*STAGE_B)

// ---- fp8 GEMM tiling: CTA 128x128, warp 64x32 (2x4), FBK=128, 3-stage, 2 CTA/SM ----
#define FN 128
#define FBK 128
#define FROWB 144
#define F_A (BM*FROWB)
#define F_B (FN*FROWB)
#define F_STAGE (F_A + F_B)
#define F_SMEM (NSTAGE*F_STAGE)

// ---- fp32 scratch ----
__device__ float g_xg   [MTOK*2*DI];
__device__ float g_delta[MTOK*DI];
__device__ float g_x2   [MTOK*DM];
// ---- bf16 Bm/Cm ----
__device__ __nv_bfloat16 g_Bm[67108864];
__device__ __nv_bfloat16 g_Cm[67108864];
// ---- bf16 activation pairs ----
__device__ __nv_bfloat16 g_xn_h [MTOK*DM],  g_xn_l [MTOK*DM];
__device__ __nv_bfloat16 g_y_h  [MTOK*DI],  g_y_l  [MTOK*DI];
__device__ __nv_bfloat16 g_xn2_h[MTOK*DM],  g_xn2_l[MTOK*DM];
__device__ __nv_bfloat16 g_h1_h [MTOK*DFF], g_h1_l [MTOK*DFF];
// ---- fp8 operands ----
__device__ __nv_fp8_e4m3 g_xc8  [MTOK*DI];
__device__ __nv_fp8_e4m3 g_WB8  [DI*DI*DS];
__device__ __nv_fp8_e4m3 g_WC8  [DI*DI*DS];
__device__ __nv_fp8_e4m3 g_Wdt8 [DI*DI];
// ---- bf16 transposed weight pairs [N,K] ----
__device__ __nv_bfloat16 g_Win_h [2*DI*DM],  g_Win_l [2*DI*DM];
__device__ __nv_bfloat16 g_Wout_h[DM*DI],    g_Wout_l[DM*DI];
__device__ __nv_bfloat16 g_W1_h  [DFF*DM],   g_W1_l  [DFF*DM];
__device__ __nv_bfloat16 g_W2_h  [DM*DFF],   g_W2_l  [DM*DFF];

// ---------------- helpers ----------------
__device__ __forceinline__ unsigned s2u(const void* p) {
    unsigned a;
    asm("{ .reg .u64 t; cvta.to.shared.u64 t, %1; cvt.u32.u64 %0, t; }" : "=r"(a) : "l"(p));
    return a;
}
__device__ __forceinline__ void cp16(unsigned d, const void* s) {
    asm volatile("cp.async.cg.shared.global [%0], [%1], 16;" :: "r"(d), "l"(s));
}
#define CP_COMMIT() asm volatile("cp.async.commit_group;" ::: "memory")
#define CP_WAIT1()  asm volatile("cp.async.wait_group 1;" ::: "memory")
#define LDSM4(r, addr) \
    asm volatile("ldmatrix.sync.aligned.m8n8.x4.shared.b16 {%0,%1,%2,%3}, [%4];" \
        : "=r"((r)[0]),"=r"((r)[1]),"=r"((r)[2]),"=r"((r)[3]) : "r"(addr))
#define MMA4(d, a, b0v, b1v) \
    asm volatile("mma.sync.aligned.m16n8k16.row.col.f32.bf16.bf16.f32 " \
        "{%0,%1,%2,%3},{%4,%5,%6,%7},{%8,%9},{%0,%1,%2,%3};" \
        : "+f"((d)[0]),"+f"((d)[1]),"+f"((d)[2]),"+f"((d)[3]) \
        : "r"((a)[0]),"r"((a)[1]),"r"((a)[2]),"r"((a)[3]),"r"(b0v),"r"(b1v))
#define MMA8(d, a, b0v, b1v) \
    asm volatile("mma.sync.aligned.m16n8k32.row.col.f32.e4m3.e4m3.f32 " \
        "{%0,%1,%2,%3},{%4,%5,%6,%7},{%8,%9},{%0,%1,%2,%3};" \
        : "+f"((d)[0]),"+f"((d)[1]),"+f"((d)[2]),"+f"((d)[3]) \
        : "r"((a)[0]),"r"((a)[1]),"r"((a)[2]),"r"((a)[3]),"r"(b0v),"r"(b1v))

__device__ __forceinline__ void split_bf16(float v, __nv_bfloat16& h, __nv_bfloat16& l) {
    h = __float2bfloat16(v);
    l = __float2bfloat16(v - __bfloat162float(h));
}

// ---------------- epilogue helper ----------------
// OMODE: 0 fp32 ; 1 bf16 hi/lo pair ; 2 bf16 single
template<int EPI, int OMODE>
__device__ __forceinline__ void epi2(int r, int c, float v0, float v1, int N,
    const float* __restrict__ bias, const float* __restrict__ add,
    float* __restrict__ outf, __nv_bfloat16* __restrict__ oh, __nv_bfloat16* __restrict__ ol)
{
    size_t go = (size_t)r*N + c;
    float2 bb = *(const float2*)&bias[c];
    v0 += bb.x; v1 += bb.y;
    if (EPI == 3) { float2 aa = *(const float2*)&add[go]; v0 += aa.x; v1 += aa.y; }
    if (EPI == 1) {
        v0 = 1.0f/(1.0f + expf(-v0))*0.099f + 0.001f;
        v1 = 1.0f/(1.0f + expf(-v1))*0.099f + 0.001f;
    }
    if (EPI == 2) {
        v0 = 0.5f*v0*(1.0f + erff(v0*0.70710678118654752f));
        v1 = 0.5f*v1*(1.0f + erff(v1*0.70710678118654752f));
    }
    if (OMODE == 1) {
        __nv_bfloat16 h0,l0,h1,l1;
        split_bf16(v0,h0,l0); split_bf16(v1,h1,l1);
        *(__nv_bfloat162*)&oh[go] = __nv_bfloat162{h0,h1};
        *(__nv_bfloat162*)&ol[go] = __nv_bfloat162{l0,l1};
    } else if (OMODE == 2) {
        *(__nv_bfloat162*)&oh[go] =
            __nv_bfloat162{__float2bfloat16(v0), __float2bfloat16(v1)};
    } else {
        float2 o; o.x = v0; o.y = v1;
        *(float2*)&outf[go] = o;
    }
}

// ---------------- bf16 split HMMA GEMM (3-term), 512 threads, BN=256 ----------------
template<int EPI, int OMODE>
__global__ __launch_bounds__(512, 1)
void hgemm(const __nv_bfloat16* __restrict__ Ah, const __nv_bfloat16* __restrict__ Al,
           const __nv_bfloat16* __restrict__ Bh, const __nv_bfloat16* __restrict__ Bl,
           int K, int N,
           const float* __restrict__ bias, const float* __restrict__ add,
           float* __restrict__ outf,
           __nv_bfloat16* __restrict__ oh, __nv_bfloat16* __restrict__ ol)
{
    extern __shared__ char sm[];
    unsigned sbase = s2u(sm);
    int tid = threadIdx.x, lane = tid & 31, wid = tid >> 5;
    int wm = wid & 3, wn = wid >> 2;             // 4x4 warps; warp tile 32 x 64
    int crow = blockIdx.x * BM, ccol = blockIdx.y * BN;

    bool aact = tid < 256;
    int arow = tid & 127, asp = (tid >> 7) & 1;
    const __nv_bfloat16* Asrc = (asp ? Al : Ah) + (size_t)(crow + arow)*K;
    unsigned adst = sbase + asp*A_SPLIT + arow*ROWB;
    int brow = tid & 255, bsp = tid >> 8;
    const __nv_bfloat16* Bsrc = (bsp ? Bl : Bh) + (size_t)(ccol + brow)*K;
    unsigned bdst = sbase + A_BOTH + bsp*B_SPLIT + brow*ROWB;

    float acc[2][8][4];
    #pragma unroll
    for (int i = 0; i < 2; i++)
        #pragma unroll
        for (int j = 0; j < 8; j++)
            #pragma unroll
            for (int q = 0; q < 4; q++) acc[i][j][q] = 0.f;

    const int nk = K / BK;

    #pragma unroll
    for (int st = 0; st < NSTAGE-1; st++) {
        unsigned so = st*STAGE_B;
        #pragma unroll
        for (int c = 0; c < 4; c++) {
            if (aact) cp16(adst + so + c*16, Asrc + st*BK + c*8);
            cp16(bdst + so + c*16, Bsrc + st*BK + c*8);
        }
        CP_COMMIT();
    }

    int rrow = lane & 15, rhalf = lane >> 4;

    for (int i = 0; i < nk; i++) {
        CP_WAIT1();
        __syncthreads();

        int j = i + NSTAGE - 1;
        if (j < nk) {
            unsigned so = (j % NSTAGE)*STAGE_B;
            #pragma unroll
            for (int c = 0; c < 4; c++) {
                if (aact) cp16(adst + so + c*16, Asrc + j*BK + c*8);
                cp16(bdst + so + c*16, Bsrc + j*BK + c*8);
            }
        }
        CP_COMMIT();

        unsigned aST = sbase + (i % NSTAGE)*STAGE_B;
        unsigned bST = aST + A_BOTH;

        #pragma unroll
        for (int ks = 0; ks < 2; ks++) {
            int koff = ks*16;
            unsigned ah[2][4], al_[2][4];
            #pragma unroll
            for (int mt = 0; mt < 2; mt++) {
                unsigned base = aST + (unsigned)(wm*32 + mt*16 + rrow)*ROWB
                              + (unsigned)(koff + rhalf*8)*2;
                LDSM4(ah[mt], base);
                LDSM4(al_[mt], base + A_SPLIT);
            }
            #pragma unroll
            for (int p = 0; p < 4; p++) {
                unsigned base = bST + (unsigned)(wn*64 + p*16 + rrow)*ROWB
                              + (unsigned)(koff + rhalf*8)*2;
                unsigned th[4], tl[4];
                LDSM4(th, base);
                LDSM4(tl, base + B_SPLIT);
                #pragma unroll
                for (int mt = 0; mt < 2; mt++) {
                    MMA4(acc[mt][2*p],   ah[mt], th[0], th[2]);
                    MMA4(acc[mt][2*p+1], ah[mt], th[1], th[3]);
                }
                #pragma unroll
                for (int mt = 0; mt < 2; mt++) {
                    MMA4(acc[mt][2*p],   ah[mt], tl[0], tl[2]);
                    MMA4(acc[mt][2*p+1], ah[mt], tl[1], tl[3]);
                }
                #pragma unroll
                for (int mt = 0; mt < 2; mt++) {
                    MMA4(acc[mt][2*p],   al_[mt], th[0], th[2]);
                    MMA4(acc[mt][2*p+1], al_[mt], th[1], th[3]);
                }
            }
        }
    }

    #pragma unroll
    for (int mt = 0; mt < 2; mt++) {
        int r0 = crow + wm*32 + mt*16 + (lane >> 2);
        #pragma unroll
        for (int nt = 0; nt < 8; nt++) {
            int c = ccol + wn*64 + nt*8 + 2*(lane & 3);
            epi2<EPI,OMODE>(r0,     c, acc[mt][nt][0], acc[mt][nt][1], N, bias, add, outf, oh, ol);
            epi2<EPI,OMODE>(r0 + 8, c, acc[mt][nt][2], acc[mt][nt][3], N, bias, add, outf, oh, ol);
        }
    }
}

// ---------------- fp8 e4m3 GEMM: CTA 128x128, 2 CTA/SM, ks-pipelined A frags ----------------
template<int EPI, int OMODE>
__global__ __launch_bounds__(256, 2)
void fgemm(const __nv_fp8_e4m3* __restrict__ A8, const __nv_fp8_e4m3* __restrict__ B8,
           int K, int N, const float* __restrict__ bias,
           float* __restrict__ outf, __nv_bfloat16* __restrict__ oh)
{
    extern __shared__ char sm[];
    unsigned sbase = s2u(sm);
    int tid = threadIdx.x, lane = tid & 31, wid = tid >> 5;
    int wm = wid & 1, wn = wid >> 1;            // 2x4 warps; warp tile 64 x 32
    int crow = blockIdx.x * BM, ccol = blockIdx.y * FN;

    int r2 = tid >> 1, hf = tid & 1;
    const char* Asrc = (const char*)(A8 + (size_t)(crow + r2)*K) + hf*64;
    const char* Bsrc = (const char*)(B8 + (size_t)(ccol + r2)*K) + hf*64;
    unsigned adst = sbase + r2*FROWB + hf*64;
    unsigned bdst = sbase + F_A + r2*FROWB + hf*64;

    float acc[4][4][4];
    #pragma unroll
    for (int i = 0; i < 4; i++)
        #pragma unroll
        for (int j = 0; j < 4; j++)
            #pragma unroll
            for (int q = 0; q < 4; q++) acc[i][j][q] = 0.f;

    const int nk = K / FBK;

    #pragma unroll
    for (int st = 0; st < NSTAGE-1; st++) {
        unsigned so = st*F_STAGE;
        #pragma unroll
        for (int c = 0; c < 4; c++) {
            cp16(adst + so + c*16, Asrc + st*FBK + c*16);
            cp16(bdst + so + c*16, Bsrc + st*FBK + c*16);
        }
        CP_COMMIT();
    }

    int rrow = lane & 15, rhalf = lane >> 4;

    for (int i = 0; i < nk; i++) {
        CP_WAIT1();
        __syncthreads();

        int j = i + NSTAGE - 1;
        if (j < nk) {
            unsigned so = (j % NSTAGE)*F_STAGE;
            #pragma unroll
            for (int c = 0; c < 4; c++) {
                cp16(adst + so + c*16, Asrc + j*FBK + c*16);
                cp16(bdst + so + c*16, Bsrc + j*FBK + c*16);
            }
        }
        CP_COMMIT();

        unsigned aST = sbase + (i % NSTAGE)*F_STAGE;
        unsigned bST = aST + F_A;

        // double-buffered A fragments: load ks+1 before ks's MMAs
        unsigned av[2][4][4];
        #pragma unroll
        for (int mt = 0; mt < 4; mt++) {
            unsigned base = aST + (unsigned)(wm*64 + mt*16 + rrow)*FROWB
                          + (unsigned)(rhalf*16);
            LDSM4(av[0][mt], base);
        }
        #pragma unroll
        for (int ks = 0; ks < 4; ks++) {
            int cur = ks & 1, nxt = cur ^ 1;
            if (ks < 3) {
                int koff2 = (ks+1)*32;
                #pragma unroll
                for (int mt = 0; mt < 4; mt++) {
                    unsigned base = aST + (unsigned)(wm*64 + mt*16 + rrow)*FROWB
                                  + (unsigned)(koff2 + rhalf*16);
                    LDSM4(av[nxt][mt], base);
                }
            }
            int koff = ks*32;
            #pragma unroll
            for (int p = 0; p < 2; p++) {
                unsigned base = bST + (unsigned)(wn*32 + p*16 + rrow)*FROWB
                              + (unsigned)(koff + rhalf*16);
                unsigned tb[4];
                LDSM4(tb, base);
                #pragma unroll
                for (int mt = 0; mt < 4; mt++) {
                    MMA8(acc[mt][2*p],   av[cur][mt], tb[0], tb[2]);
                    MMA8(acc[mt][2*p+1], av[cur][mt], tb[1], tb[3]);
                }
            }
        }
    }

    #pragma unroll
    for (int mt = 0; mt < 4; mt++) {
        int r0 = crow + wm*64 + mt*16 + (lane >> 2);
        #pragma unroll
        for (int nt = 0; nt < 4; nt++) {
            int c = ccol + wn*32 + nt*8 + 2*(lane & 3);
            epi2<EPI,OMODE>(r0,     c, acc[mt][nt][0], acc[mt][nt][1], N, bias, nullptr, outf, oh, nullptr);
            epi2<EPI,OMODE>(r0 + 8, c, acc[mt][nt][2], acc[mt][nt][3], N, bias, nullptr, outf, oh, nullptr);
        }
    }
}

// ---------------- weight transpose kernels (vectorized stores) ----------------
__global__ __launch_bounds__(256)
void wtrans(const float* __restrict__ W, __nv_bfloat16* __restrict__ hi,
            __nv_bfloat16* __restrict__ lo, int K, int N)
{
    __shared__ float t[32][33];
    int n0 = blockIdx.x*32, k0 = blockIdx.y*32;
    int tx = threadIdx.x, ty = threadIdx.y;
    #pragma unroll
    for (int i = 0; i < 4; i++)
        t[ty + i*8][tx] = W[(size_t)(k0 + ty + i*8)*N + n0 + tx];
    __syncthreads();
    int flat = ty*32 + tx;
    int nl = flat >> 3, k4 = (flat & 7)*4;
    __nv_bfloat16 h[4], l[4];
    #pragma unroll
    for (int j = 0; j < 4; j++) split_bf16(t[k4+j][nl], h[j], l[j]);
    size_t o = (size_t)(n0 + nl)*K + k0 + k4;
    uint2 ph, pl;
    ph.x = ((unsigned)__bfloat16_as_ushort(h[1]) << 16) | __bfloat16_as_ushort(h[0]);
    ph.y = ((unsigned)__bfloat16_as_ushort(h[3]) << 16) | __bfloat16_as_ushort(h[2]);
    pl.x = ((unsigned)__bfloat16_as_ushort(l[1]) << 16) | __bfloat16_as_ushort(l[0]);
    pl.y = ((unsigned)__bfloat16_as_ushort(l[3]) << 16) | __bfloat16_as_ushort(l[2]);
    *(uint2*)&hi[o] = ph;
    *(uint2*)&lo[o] = pl;
}
// batched fp8 transpose: blockIdx.z selects (W_B->WB8) or (W_C->WC8)
__global__ __launch_bounds__(256)
void wtrans8_2(const float* __restrict__ W0, const float* __restrict__ W1s,
               __nv_fp8_e4m3* __restrict__ o0, __nv_fp8_e4m3* __restrict__ o1,
               int K, int N)
{
    const float* W = blockIdx.z ? W1s : W0;
    __nv_fp8_e4m3* o8 = blockIdx.z ? o1 : o0;
    __shared__ float t[32][33];
    int n0 = blockIdx.x*32, k0 = blockIdx.y*32;
    int tx = threadIdx.x, ty = threadIdx.y;
    #pragma unroll
    for (int i = 0; i < 4; i++)
        t[ty + i*8][tx] = W[(size_t)(k0 + ty + i*8)*N + n0 + tx];
    __syncthreads();
    int flat = ty*32 + tx;
    int nl = flat >> 3, k4 = (flat & 7)*4;
    unsigned pk = 0;
    #pragma unroll
    for (int j = 0; j < 4; j++) {
        __nv_fp8_e4m3 v(t[k4+j][nl]);
        pk |= (unsigned)(*(unsigned char*)&v) << (j*8);
    }
    *(unsigned*)&o8[(size_t)(n0 + nl)*K + k0 + k4] = pk;
}
__global__ __launch_bounds__(256)
void wtrans8(const float* __restrict__ W, __nv_fp8_e4m3* __restrict__ o8, int K, int N)
{
    __shared__ float t[32][33];
    int n0 = blockIdx.x*32, k0 = blockIdx.y*32;
    int tx = threadIdx.x, ty = threadIdx.y;
    #pragma unroll
    for (int i = 0; i < 4; i++)
        t[ty + i*8][tx] = W[(size_t)(k0 + ty + i*8)*N + n0 + tx];
    __syncthreads();
    int flat = ty*32 + tx;
    int nl = flat >> 3, k4 = (flat & 7)*4;
    unsigned pk = 0;
    #pragma unroll
    for (int j = 0; j < 4; j++) {
        __nv_fp8_e4m3 v(t[k4+j][nl]);
        pk |= (unsigned)(*(unsigned char*)&v) << (j*8);
    }
    *(unsigned*)&o8[(size_t)(n0 + nl)*K + k0 + k4] = pk;
}

// ---------------- LayerNorm -> bf16 pair ----------------
__global__ __launch_bounds__(256)
void ln_kernel(const float* __restrict__ in, const float* __restrict__ g,
               const float* __restrict__ bcoef,
               __nv_bfloat16* __restrict__ oh, __nv_bfloat16* __restrict__ ol)
{
    int row = blockIdx.x, tid = threadIdx.x;
    float4 v = ((const float4*)(in + (size_t)row*DM))[tid];
    __shared__ float red1[8], red2[8];
    float s = v.x + v.y + v.z + v.w;
    #pragma unroll
    for (int o = 16; o > 0; o >>= 1) s += __shfl_xor_sync(0xffffffffu, s, o);
    if ((tid & 31) == 0) red1[tid >> 5] = s;
    __syncthreads();
    float tot = 0.f;
    #pragma unroll
    for (int i = 0; i < 8; i++) tot += red1[i];
    float mean = tot * (1.0f/DM);
    float dx = v.x-mean, dy = v.y-mean, dz = v.z-mean, dw = v.w-mean;
    float sq = dx*dx + dy*dy + dz*dz + dw*dw;
    #pragma unroll
    for (int o = 16; o > 0; o >>= 1) sq += __shfl_xor_sync(0xffffffffu, sq, o);
    if ((tid & 31) == 0) red2[tid >> 5] = sq;
    __syncthreads();
    float tot2 = 0.f;
    #pragma unroll
    for (int i = 0; i < 8; i++) tot2 += red2[i];
    float rstd = rsqrtf(tot2*(1.0f/DM) + 1e-5f);
    float4 gg = ((const float4*)g)[tid];
    float4 bb = ((const float4*)bcoef)[tid];
    float o0 = dx*rstd*gg.x+bb.x, o1 = dy*rstd*gg.y+bb.y;
    float o2 = dz*rstd*gg.z+bb.z, o3 = dw*rstd*gg.w+bb.w;
    __nv_bfloat16 h0,l0,h1,l1,h2,l2,h3,l3;
    split_bf16(o0,h0,l0); split_bf16(o1,h1,l1); split_bf16(o2,h2,l2); split_bf16(o3,h3,l3);
    __nv_bfloat162* ph = (__nv_bfloat162*)(oh + (size_t)row*DM);
    __nv_bfloat162* pl = (__nv_bfloat162*)(ol + (size_t)row*DM);
    ph[tid*2] = __nv_bfloat162{h0,h1}; ph[tid*2+1] = __nv_bfloat162{h2,h3};
    pl[tid*2] = __nv_bfloat162{l0,l1}; pl[tid*2+1] = __nv_bfloat162{l2,l3};
}

// ---------------- conv -> fp8 only ----------------
__global__ __launch_bounds__(256)
void conv_kernel(const float* __restrict__ xg, const float* __restrict__ cw,
                 const float* __restrict__ cb, __nv_fp8_e4m3* __restrict__ o8)
{
    int idx = blockIdx.x*blockDim.x + threadIdx.x;
    int d = idx & (DI-1);
    int token = idx >> 11;
    int t = token & (SEQ-1);
    float acc = cb[d];
    #pragma unroll
    for (int k = 0; k < 4; k++) {
        int ts = t - 3 + k;
        if (ts >= 0) acc += xg[(size_t)(token-3+k)*(2*DI) + d] * cw[d*4+k];
    }
    o8[idx] = __nv_fp8_e4m3(acc);
}

// ---------------- selective scan: chunked software pipeline ----------------
#define SCH 8
__global__ __launch_bounds__(256)
void scan_kernel(const float* __restrict__ xg, const float* __restrict__ delta,
                 const __nv_bfloat16* __restrict__ Bm, const __nv_bfloat16* __restrict__ Cm,
                 const float* __restrict__ A_log, const float* __restrict__ Dp,
                 __nv_bfloat16* __restrict__ yh, __nv_bfloat16* __restrict__ yl)
{
    int tid = blockIdx.x*blockDim.x + threadIdx.x;
    int n = tid & (DS-1);
    int d = (tid >> 4) & (DI-1);
    int b = tid >> 15;
    float Aneg = -expf(A_log[d*DS + n]);
    float Dval = Dp[d];
    float h = 0.f;
    int base_tok = b*SEQ;

    float dvA[SCH], xpA[SCH], bmA[SCH], cmA[SCH];
    float dvB[SCH], xpB[SCH], bmB[SCH], cmB[SCH];

#define SC_LOAD(dv_, xp_, bm_, cm_, K0) do { \
    _Pragma("unroll") \
    for (int i = 0; i < SCH; i++) { \
        int t_ = (K0) + i; t_ = t_ < SEQ ? t_ : SEQ-1; \
        int tk = base_tok + t_; \
        dv_[i] = delta[(size_t)tk*DI + d]; \
        xp_[i] = xg[(size_t)tk*(2*DI) + d]; \
        bm_[i] = __bfloat162float(Bm[(size_t)tk*(DI*DS) + d*DS + n]); \
        cm_[i] = __bfloat162float(Cm[(size_t)tk*(DI*DS) + d*DS + n]); \
    } } while (0)

#define SC_COMP(dv_, xp_, bm_, cm_, K0) do { \
    _Pragma("unroll") \
    for (int i = 0; i < SCH; i++) { \
        int tk = base_tok + (K0) + i; \
        float a_ = __expf(dv_[i]*Aneg); \
        h = a_*h + (dv_[i]*bm_[i])*xp_[i]; \
        float yv = cm_[i]*h; \
        yv += __shfl_xor_sync(0xffffffffu, yv, 1); \
        yv += __shfl_xor_sync(0xffffffffu, yv, 2); \
        yv += __shfl_xor_sync(0xffffffffu, yv, 4); \
        yv += __shfl_xor_sync(0xffffffffu, yv, 8); \
        if (n == 0) { \
            float g_ = xg[(size_t)tk*(2*DI) + DI + d]; \
            float sg = g_ / (1.0f + __expf(-g_)); \
            float val = (yv + Dval*xp_[i])*sg; \
            __nv_bfloat16 hh, ll; split_bf16(val, hh, ll); \
            yh[(size_t)tk*DI + d] = hh; \
            yl[(size_t)tk*DI + d] = ll; \
        } \
    } } while (0)

    SC_LOAD(dvA, xpA, bmA, cmA, 0);
    for (int k0 = 0; k0 < SEQ; k0 += 2*SCH) {
        SC_LOAD(dvB, xpB, bmB, cmB, k0 + SCH);
        SC_COMP(dvA, xpA, bmA, cmA, k0);
        SC_LOAD(dvA, xpA, bmA, cmA, k0 + 2*SCH);
        SC_COMP(dvB, xpB, bmB, cmB, k0 + SCH);
    }
#undef SC_LOAD
#undef SC_COMP
}

// ---------------- host ----------------
template<int EPI, int OMODE>
static void launch_hgemm(const __nv_bfloat16* Ah, const __nv_bfloat16* Al,
                         const __nv_bfloat16* Bh, const __nv_bfloat16* Bl,
                         int K, int N, const float* bias, const float* add,
                         float* outf, __nv_bfloat16* oh, __nv_bfloat16* ol)
{
    cudaFuncSetAttribute(hgemm<EPI,OMODE>, cudaFuncAttributeMaxDynamicSharedMemorySize, SMEM_B);
    hgemm<EPI,OMODE><<<dim3(MTOK/BM, N/BN), 512, SMEM_B>>>(Ah, Al, Bh, Bl, K, N,
                                                            bias, add, outf, oh, ol);
}
template<int EPI, int OMODE>
static void launch_fgemm(const __nv_fp8_e4m3* A8, const __nv_fp8_e4m3* B8,
                         int K, int N, const float* bias,
                         float* outf, __nv_bfloat16* oh)
{
    cudaFuncSetAttribute(fgemm<EPI,OMODE>, cudaFuncAttributeMaxDynamicSharedMemorySize, F_SMEM);
    fgemm<EPI,OMODE><<<dim3(MTOK/BM, N/FN), 256, F_SMEM>>>(A8, B8, K, N, bias, outf, oh);
}

extern "C" void kernel_launch(void* const* d_in, const int* in_sizes, int n_in,
                              void* d_out, int out_size)
{
    const float* x      = (const float*)d_in[0];
    const float* ln1_g  = (const float*)d_in[1];
    const float* ln1_b  = (const float*)d_in[2];
    const float* W_in   = (const float*)d_in[3];
    const float* b_in   = (const float*)d_in[4];
    const float* conv_w = (const float*)d_in[5];
    const float* conv_b = (const float*)d_in[6];
    const float* A_log  = (const float*)d_in[7];
    const float* W_B    = (const float*)d_in[8];
    const float* b_B    = (const float*)d_in[9];
    const float* W_C    = (const float*)d_in[10];
    const float* b_C    = (const float*)d_in[11];
    const float* Dp     = (const float*)d_in[12];
    const float* W_dt   = (const float*)d_in[13];
    const float* b_dt   = (const float*)d_in[14];
    const float* W_out  = (const float*)d_in[15];
    const float* b_out  = (const float*)d_in[16];
    const float* ln2_g  = (const float*)d_in[17];
    const float* ln2_b  = (const float*)d_in[18];
    const float* W1     = (const float*)d_in[19];
    const float* b1     = (const float*)d_in[20];
    const float* W2     = (const float*)d_in[21];
    const float* b2     = (const float*)d_in[22];
    float* out = (float*)d_out;

    float *xg, *delta, *x2;
    cudaGetSymbolAddress((void**)&xg, g_xg);
    cudaGetSymbolAddress((void**)&delta, g_delta);
    cudaGetSymbolAddress((void**)&x2, g_x2);
    __nv_bfloat16 *Bm, *Cm;
    cudaGetSymbolAddress((void**)&Bm, g_Bm);
    cudaGetSymbolAddress((void**)&Cm, g_Cm);
    __nv_bfloat16 *xnh,*xnl,*yh,*yl,*xn2h,*xn2l,*h1h,*h1l;
    cudaGetSymbolAddress((void**)&xnh, g_xn_h);   cudaGetSymbolAddress((void**)&xnl, g_xn_l);
    cudaGetSymbolAddress((void**)&yh,  g_y_h);    cudaGetSymbolAddress((void**)&yl,  g_y_l);
    cudaGetSymbolAddress((void**)&xn2h,g_xn2_h);  cudaGetSymbolAddress((void**)&xn2l,g_xn2_l);
    cudaGetSymbolAddress((void**)&h1h, g_h1_h);   cudaGetSymbolAddress((void**)&h1l, g_h1_l);
    __nv_fp8_e4m3 *xc8, *WB8, *WC8, *Wdt8;
    cudaGetSymbolAddress((void**)&xc8, g_xc8);
    cudaGetSymbolAddress((void**)&WB8, g_WB8);
    cudaGetSymbolAddress((void**)&WC8, g_WC8);
    cudaGetSymbolAddress((void**)&Wdt8, g_Wdt8);
    __nv_bfloat16 *Winh,*Winl,*Wouth,*Woutl,*W1h,*W1l,*W2h,*W2l;
    cudaGetSymbolAddress((void**)&Winh, g_Win_h); cudaGetSymbolAddress((void**)&Winl, g_Win_l);
    cudaGetSymbolAddress((void**)&Wouth,g_Wout_h);cudaGetSymbolAddress((void**)&Woutl,g_Wout_l);
    cudaGetSymbolAddress((void**)&W1h,  g_W1_h);  cudaGetSymbolAddress((void**)&W1l,  g_W1_l);
    cudaGetSymbolAddress((void**)&W2h,  g_W2_h);  cudaGetSymbolAddress((void**)&W2l,  g_W2_l);

    dim3 tb(32, 8);
    // keep my launch index 3 = hgemm<0,0> (ncu captures it)
    wtrans <<<dim3((2*DI)/32, DM/32),  tb>>>(W_in, Winh, Winl, DM, 2*DI);            // 0
    ln_kernel<<<MTOK, 256>>>(x, ln1_g, ln1_b, xnh, xnl);                             // 1
    wtrans8_2<<<dim3((DI*DS)/32, DI/32, 2), tb>>>(W_B, W_C, WB8, WC8, DI, DI*DS);    // 2
    launch_hgemm<0,0>(xnh, xnl, Winh, Winl, DM, 2*DI, b_in, nullptr, xg, nullptr, nullptr); // 3 <- profiled
    conv_kernel<<<(MTOK*DI)/256, 256>>>(xg, conv_w, conv_b, xc8);                    // 4
    launch_fgemm<0,2>(xc8, WB8, DI, DI*DS, b_B, nullptr, Bm);                        // 5
    launch_fgemm<0,2>(xc8, WC8, DI, DI*DS, b_C, nullptr, Cm);                        // 6
    wtrans8<<<dim3(DI/32, DI/32),      tb>>>(W_dt, Wdt8, DI, DI);                    // 7
    launch_fgemm<1,0>(xc8, Wdt8, DI, DI, b_dt, delta, nullptr);                      // 8
    scan_kernel<<<256, 256>>>(xg, delta, Bm, Cm, A_log, Dp, yh, yl);                 // 9
    wtrans <<<dim3(DM/32, DI/32),      tb>>>(W_out, Wouth, Woutl, DI, DM);           // 10
    launch_hgemm<3,0>(yh, yl, Wouth, Woutl, DI, DM, b_out, x, x2, nullptr, nullptr); // 11
    ln_kernel<<<MTOK, 256>>>(x2, ln2_g, ln2_b, xn2h, xn2l);                          // 12
    wtrans <<<dim3(DFF/32, DM/32),     tb>>>(W1, W1h, W1l, DM, DFF);                 // 13
    launch_hgemm<2,1>(xn2h, xn2l, W1h, W1l, DM, DFF, b1, nullptr, nullptr, h1h, h1l);// 14
    wtrans <<<dim3(DM/32, DFF/32),     tb>>>(W2, W2h, W2l, DFF, DM);                 // 15
    launch_hgemm<3,0>(h1h, h1l, W2h, W2l, DFF, DM, b2, x2, out, nullptr, nullptr);   // 16
}

// round 15
// speedup vs baseline: 1.0625x; 1.0625x over previous
#include <cuda_runtime.h>
#include <cuda_bf16.h>
#include <cuda_fp8.h>
#include <math.h>

#define B_SZ 2
#define SEQ  1024
#define DM   1024
#define DI   2048
#define DS   16
#define DFF  4096
#define MTOK (B_SZ*SEQ)

// ---- bf16 GEMM tiling: CTA 128x256, 512 thr (4x4 warps), BK=32, 3-stage ----
#define BM 128
#define BN 256
#define BK 32
#define NSTAGE 3
#define ROWB 80
#define A_SPLIT (BM*ROWB)
#define A_BOTH  (2*A_SPLIT)
#define B_SPLIT (BN*ROWB)
#define B_BOTH  (2*B_SPLIT)
#define STAGE_B (A_BOTH + B_BOTH)
#define SMEM_B  (NSTAGE*STAGE_B)

// ---- fp8 GEMM tiling: CTA 128x128, warp 64x32 (2x4), FBK=128, 3-stage, 2 CTA/SM ----
#define FN 128
#define FBK 128
#define FROWB 144
#define F_A (BM*FROWB)
#define F_B (FN*FROWB)
#define F_STAGE (F_A + F_B)
#define F_SMEM (NSTAGE*F_STAGE)

// ---- fp32 scratch ----
__device__ float g_xg   [MTOK*2*DI];
__device__ float g_delta[MTOK*DI];
__device__ float g_x2   [MTOK*DM];
// ---- bf16 Bm/Cm ----
__device__ __nv_bfloat16 g_Bm[67108864];
__device__ __nv_bfloat16 g_Cm[67108864];
// ---- bf16 activation pairs ----
__device__ __nv_bfloat16 g_xn_h [MTOK*DM],  g_xn_l [MTOK*DM];
__device__ __nv_bfloat16 g_y_h  [MTOK*DI],  g_y_l  [MTOK*DI];
__device__ __nv_bfloat16 g_xn2_h[MTOK*DM],  g_xn2_l[MTOK*DM];
__device__ __nv_bfloat16 g_h1_h [MTOK*DFF], g_h1_l [MTOK*DFF];
// ---- fp8 operands ----
__device__ __nv_fp8_e4m3 g_xc8  [MTOK*DI];
__device__ __nv_fp8_e4m3 g_WB8  [DI*DI*DS];
__device__ __nv_fp8_e4m3 g_WC8  [DI*DI*DS];
__device__ __nv_fp8_e4m3 g_Wdt8 [DI*DI];
// ---- bf16 transposed weight pairs [N,K] ----
__device__ __nv_bfloat16 g_Win_h [2*DI*DM],  g_Win_l [2*DI*DM];
__device__ __nv_bfloat16 g_Wout_h[DM*DI],    g_Wout_l[DM*DI];
__device__ __nv_bfloat16 g_W1_h  [DFF*DM],   g_W1_l  [DFF*DM];
__device__ __nv_bfloat16 g_W2_h  [DM*DFF],   g_W2_l  [DM*DFF];

// ---------------- helpers ----------------
__device__ __forceinline__ unsigned s2u(const void* p) {
    unsigned a;
    asm("{ .reg .u64 t; cvta.to.shared.u64 t, %1; cvt.u32.u64 %0, t; }" : "=r"(a) : "l"(p));
    return a;
}
__device__ __forceinline__ void cp16(unsigned d, const void* s) {
    asm volatile("cp.async.cg.shared.global [%0], [%1], 16;" :: "r"(d), "l"(s));
}
#define CP_COMMIT() asm volatile("cp.async.commit_group;" ::: "memory")
#define CP_WAIT1()  asm volatile("cp.async.wait_group 1;" ::: "memory")
#define LDSM4(r, addr) \
    asm volatile("ldmatrix.sync.aligned.m8n8.x4.shared.b16 {%0,%1,%2,%3}, [%4];" \
        : "=r"((r)[0]),"=r"((r)[1]),"=r"((r)[2]),"=r"((r)[3]) : "r"(addr))
#define MMA4(d, a, b0v, b1v) \
    asm volatile("mma.sync.aligned.m16n8k16.row.col.f32.bf16.bf16.f32 " \
        "{%0,%1,%2,%3},{%4,%5,%6,%7},{%8,%9},{%0,%1,%2,%3};" \
        : "+f"((d)[0]),"+f"((d)[1]),"+f"((d)[2]),"+f"((d)[3]) \
        : "r"((a)[0]),"r"((a)[1]),"r"((a)[2]),"r"((a)[3]),"r"(b0v),"r"(b1v))
#define MMA8(d, a, b0v, b1v) \
    asm volatile("mma.sync.aligned.m16n8k32.row.col.f32.e4m3.e4m3.f32 " \
        "{%0,%1,%2,%3},{%4,%5,%6,%7},{%8,%9},{%0,%1,%2,%3};" \
        : "+f"((d)[0]),"+f"((d)[1]),"+f"((d)[2]),"+f"((d)[3]) \
        : "r"((a)[0]),"r"((a)[1]),"r"((a)[2]),"r"((a)[3]),"r"(b0v),"r"(b1v))

__device__ __forceinline__ void split_bf16(float v, __nv_bfloat16& h, __nv_bfloat16& l) {
    h = __float2bfloat16(v);
    l = __float2bfloat16(v - __bfloat162float(h));
}

// ---------------- epilogue helper ----------------
// OMODE: 0 fp32 ; 1 bf16 hi/lo pair ; 2 bf16 single
template<int EPI, int OMODE>
__device__ __forceinline__ void epi2(int r, int c, float v0, float v1, int N,
    const float* __restrict__ bias, const float* __restrict__ add,
    float* __restrict__ outf, __nv_bfloat16* __restrict__ oh, __nv_bfloat16* __restrict__ ol)
{
    size_t go = (size_t)r*N + c;
    float2 bb = *(const float2*)&bias[c];
    v0 += bb.x; v1 += bb.y;
    if (EPI == 3) { float2 aa = *(const float2*)&add[go]; v0 += aa.x; v1 += aa.y; }
    if (EPI == 1) {
        v0 = 1.0f/(1.0f + expf(-v0))*0.099f + 0.001f;
        v1 = 1.0f/(1.0f + expf(-v1))*0.099f + 0.001f;
    }
    if (EPI == 2) {
        v0 = 0.5f*v0*(1.0f + erff(v0*0.70710678118654752f));
        v1 = 0.5f*v1*(1.0f + erff(v1*0.70710678118654752f));
    }
    if (OMODE == 1) {
        __nv_bfloat16 h0,l0,h1,l1;
        split_bf16(v0,h0,l0); split_bf16(v1,h1,l1);
        *(__nv_bfloat162*)&oh[go] = __nv_bfloat162{h0,h1};
        *(__nv_bfloat162*)&ol[go] = __nv_bfloat162{l0,l1};
    } else if (OMODE == 2) {
        *(__nv_bfloat162*)&oh[go] =
            __nv_bfloat162{__float2bfloat16(v0), __float2bfloat16(v1)};
    } else {
        float2 o; o.x = v0; o.y = v1;
        *(float2*)&outf[go] = o;
    }
}

// ---------------- bf16 split HMMA GEMM (3-term), 512 threads, BN=256 ----------------
template<int EPI, int OMODE>
__global__ __launch_bounds__(512, 1)
void hgemm(const __nv_bfloat16* __restrict__ Ah, const __nv_bfloat16* __restrict__ Al,
           const __nv_bfloat16* __restrict__ Bh, const __nv_bfloat16* __restrict__ Bl,
           int K, int N,
           const float* __restrict__ bias, const float* __restrict__ add,
           float* __restrict__ outf,
           __nv_bfloat16* __restrict__ oh, __nv_bfloat16* __restrict__ ol)
{
    extern __shared__ char sm[];
    unsigned sbase = s2u(sm);
    int tid = threadIdx.x, lane = tid & 31, wid = tid >> 5;
    int wm = wid & 3, wn = wid >> 2;             // 4x4 warps; warp tile 32 x 64
    int crow = blockIdx.x * BM, ccol = blockIdx.y * BN;

    bool aact = tid < 256;
    int arow = tid & 127, asp = (tid >> 7) & 1;
    const __nv_bfloat16* Asrc = (asp ? Al : Ah) + (size_t)(crow + arow)*K;
    unsigned adst = sbase + asp*A_SPLIT + arow*ROWB;
    int brow = tid & 255, bsp = tid >> 8;
    const __nv_bfloat16* Bsrc = (bsp ? Bl : Bh) + (size_t)(ccol + brow)*K;
    unsigned bdst = sbase + A_BOTH + bsp*B_SPLIT + brow*ROWB;

    float acc[2][8][4];
    #pragma unroll
    for (int i = 0; i < 2; i++)
        #pragma unroll
        for (int j = 0; j < 8; j++)
            #pragma unroll
            for (int q = 0; q < 4; q++) acc[i][j][q] = 0.f;

    const int nk = K / BK;

    #pragma unroll
    for (int st = 0; st < NSTAGE-1; st++) {
        unsigned so = st*STAGE_B;
        #pragma unroll
        for (int c = 0; c < 4; c++) {
            if (aact) cp16(adst + so + c*16, Asrc + st*BK + c*8);
            cp16(bdst + so + c*16, Bsrc + st*BK + c*8);
        }
        CP_COMMIT();
    }

    int rrow = lane & 15, rhalf = lane >> 4;

    for (int i = 0; i < nk; i++) {
        CP_WAIT1();
        __syncthreads();

        int j = i + NSTAGE - 1;
        if (j < nk) {
            unsigned so = (j % NSTAGE)*STAGE_B;
            #pragma unroll
            for (int c = 0; c < 4; c++) {
                if (aact) cp16(adst + so + c*16, Asrc + j*BK + c*8);
                cp16(bdst + so + c*16, Bsrc + j*BK + c*8);
            }
        }
        CP_COMMIT();

        unsigned aST = sbase + (i % NSTAGE)*STAGE_B;
        unsigned bST = aST + A_BOTH;

        #pragma unroll
        for (int ks = 0; ks < 2; ks++) {
            int koff = ks*16;
            unsigned ah[2][4], al_[2][4];
            #pragma unroll
            for (int mt = 0; mt < 2; mt++) {
                unsigned base = aST + (unsigned)(wm*32 + mt*16 + rrow)*ROWB
                              + (unsigned)(koff + rhalf*8)*2;
                LDSM4(ah[mt], base);
                LDSM4(al_[mt], base + A_SPLIT);
            }
            #pragma unroll
            for (int p = 0; p < 4; p++) {
                unsigned base = bST + (unsigned)(wn*64 + p*16 + rrow)*ROWB
                              + (unsigned)(koff + rhalf*8)*2;
                unsigned th[4], tl[4];
                LDSM4(th, base);
                LDSM4(tl, base + B_SPLIT);
                #pragma unroll
                for (int mt = 0; mt < 2; mt++) {
                    MMA4(acc[mt][2*p],   ah[mt],  th[0], th[2]);
                    MMA4(acc[mt][2*p+1], ah[mt],  th[1], th[3]);
                    MMA4(acc[mt][2*p],   ah[mt],  tl[0], tl[2]);
                    MMA4(acc[mt][2*p+1], ah[mt],  tl[1], tl[3]);
                    MMA4(acc[mt][2*p],   al_[mt], th[0], th[2]);
                    MMA4(acc[mt][2*p+1], al_[mt], th[1], th[3]);
                }
            }
        }
    }

    #pragma unroll
    for (int mt = 0; mt < 2; mt++) {
        int r0 = crow + wm*32 + mt*16 + (lane >> 2);
        #pragma unroll
        for (int nt = 0; nt < 8; nt++) {
            int c = ccol + wn*64 + nt*8 + 2*(lane & 3);
            epi2<EPI,OMODE>(r0,     c, acc[mt][nt][0], acc[mt][nt][1], N, bias, add, outf, oh, ol);
            epi2<EPI,OMODE>(r0 + 8, c, acc[mt][nt][2], acc[mt][nt][3], N, bias, add, outf, oh, ol);
        }
    }
}

// ---------------- fp8 e4m3 GEMM core (R12 body) ----------------
template<int EPI, int OMODE>
__device__ __forceinline__ void fgemm_body(
    const __nv_fp8_e4m3* __restrict__ A8, const __nv_fp8_e4m3* __restrict__ B8,
    int K, int N, const float* __restrict__ bias,
    float* __restrict__ outf, __nv_bfloat16* __restrict__ oh, char* sm)
{
    unsigned sbase = s2u(sm);
    int tid = threadIdx.x, lane = tid & 31, wid = tid >> 5;
    int wm = wid & 1, wn = wid >> 1;            // 2x4 warps; warp tile 64 x 32
    int crow = blockIdx.x * BM, ccol = blockIdx.y * FN;

    int r2 = tid >> 1, hf = tid & 1;
    const char* Asrc = (const char*)(A8 + (size_t)(crow + r2)*K) + hf*64;
    const char* Bsrc = (const char*)(B8 + (size_t)(ccol + r2)*K) + hf*64;
    unsigned adst = sbase + r2*FROWB + hf*64;
    unsigned bdst = sbase + F_A + r2*FROWB + hf*64;

    float acc[4][4][4];
    #pragma unroll
    for (int i = 0; i < 4; i++)
        #pragma unroll
        for (int j = 0; j < 4; j++)
            #pragma unroll
            for (int q = 0; q < 4; q++) acc[i][j][q] = 0.f;

    const int nk = K / FBK;

    #pragma unroll
    for (int st = 0; st < NSTAGE-1; st++) {
        unsigned so = st*F_STAGE;
        #pragma unroll
        for (int c = 0; c < 4; c++) {
            cp16(adst + so + c*16, Asrc + st*FBK + c*16);
            cp16(bdst + so + c*16, Bsrc + st*FBK + c*16);
        }
        CP_COMMIT();
    }

    int rrow = lane & 15, rhalf = lane >> 4;

    for (int i = 0; i < nk; i++) {
        CP_WAIT1();
        __syncthreads();

        int j = i + NSTAGE - 1;
        if (j < nk) {
            unsigned so = (j % NSTAGE)*F_STAGE;
            #pragma unroll
            for (int c = 0; c < 4; c++) {
                cp16(adst + so + c*16, Asrc + j*FBK + c*16);
                cp16(bdst + so + c*16, Bsrc + j*FBK + c*16);
            }
        }
        CP_COMMIT();

        unsigned aST = sbase + (i % NSTAGE)*F_STAGE;
        unsigned bST = aST + F_A;

        #pragma unroll
        for (int ks = 0; ks < 4; ks++) {
            int koff = ks*32;
            unsigned av[4][4];
            #pragma unroll
            for (int mt = 0; mt < 4; mt++) {
                unsigned base = aST + (unsigned)(wm*64 + mt*16 + rrow)*FROWB
                              + (unsigned)(koff + rhalf*16);
                LDSM4(av[mt], base);
            }
            #pragma unroll
            for (int p = 0; p < 2; p++) {
                unsigned base = bST + (unsigned)(wn*32 + p*16 + rrow)*FROWB
                              + (unsigned)(koff + rhalf*16);
                unsigned tb[4];
                LDSM4(tb, base);
                #pragma unroll
                for (int mt = 0; mt < 4; mt++) {
                    MMA8(acc[mt][2*p],   av[mt], tb[0], tb[2]);
                    MMA8(acc[mt][2*p+1], av[mt], tb[1], tb[3]);
                }
            }
        }
    }

    #pragma unroll
    for (int mt = 0; mt < 4; mt++) {
        int r0 = crow + wm*64 + mt*16 + (lane >> 2);
        #pragma unroll
        for (int nt = 0; nt < 4; nt++) {
            int c = ccol + wn*32 + nt*8 + 2*(lane & 3);
            epi2<EPI,OMODE>(r0,     c, acc[mt][nt][0], acc[mt][nt][1], N, bias, nullptr, outf, oh, nullptr);
            epi2<EPI,OMODE>(r0 + 8, c, acc[mt][nt][2], acc[mt][nt][3], N, bias, nullptr, outf, oh, nullptr);
        }
    }
}

// single GEMM (delta path)
template<int EPI, int OMODE>
__global__ __launch_bounds__(256, 2)
void fgemm(const __nv_fp8_e4m3* __restrict__ A8, const __nv_fp8_e4m3* __restrict__ B8,
           int K, int N, const float* __restrict__ bias,
           float* __restrict__ outf, __nv_bfloat16* __restrict__ oh)
{
    extern __shared__ char sm[];
    fgemm_body<EPI,OMODE>(A8, B8, K, N, bias, outf, oh, sm);
}

// merged Bm/Cm GEMM: blockIdx.z selects (WB8->Bm) or (WC8->Cm)
__global__ __launch_bounds__(256, 2)
void fgemm2(const __nv_fp8_e4m3* __restrict__ A8,
            const __nv_fp8_e4m3* __restrict__ B0, const __nv_fp8_e4m3* __restrict__ B1,
            int K, int N, const float* __restrict__ bias0, const float* __restrict__ bias1,
            __nv_bfloat16* __restrict__ o0, __nv_bfloat16* __restrict__ o1)
{
    extern __shared__ char sm[];
    const __nv_fp8_e4m3* B8 = blockIdx.z ? B1 : B0;
    const float* bias = blockIdx.z ? bias1 : bias0;
    __nv_bfloat16* oh = blockIdx.z ? o1 : o0;
    fgemm_body<0,2>(A8, B8, K, N, bias, nullptr, oh, sm);
}

// ---------------- weight transpose kernels (vectorized stores) ----------------
__global__ __launch_bounds__(256)
void wtrans(const float* __restrict__ W, __nv_bfloat16* __restrict__ hi,
            __nv_bfloat16* __restrict__ lo, int K, int N)
{
    __shared__ float t[32][33];
    int n0 = blockIdx.x*32, k0 = blockIdx.y*32;
    int tx = threadIdx.x, ty = threadIdx.y;
    #pragma unroll
    for (int i = 0; i < 4; i++)
        t[ty + i*8][tx] = W[(size_t)(k0 + ty + i*8)*N + n0 + tx];
    __syncthreads();
    int flat = ty*32 + tx;
    int nl = flat >> 3, k4 = (flat & 7)*4;
    __nv_bfloat16 h[4], l[4];
    #pragma unroll
    for (int j = 0; j < 4; j++) split_bf16(t[k4+j][nl], h[j], l[j]);
    size_t o = (size_t)(n0 + nl)*K + k0 + k4;
    uint2 ph, pl;
    ph.x = ((unsigned)__bfloat16_as_ushort(h[1]) << 16) | __bfloat16_as_ushort(h[0]);
    ph.y = ((unsigned)__bfloat16_as_ushort(h[3]) << 16) | __bfloat16_as_ushort(h[2]);
    pl.x = ((unsigned)__bfloat16_as_ushort(l[1]) << 16) | __bfloat16_as_ushort(l[0]);
    pl.y = ((unsigned)__bfloat16_as_ushort(l[3]) << 16) | __bfloat16_as_ushort(l[2]);
    *(uint2*)&hi[o] = ph;
    *(uint2*)&lo[o] = pl;
}
// batched fp8 transpose: blockIdx.z selects (W_B->WB8) or (W_C->WC8)
__global__ __launch_bounds__(256)
void wtrans8_2(const float* __restrict__ W0, const float* __restrict__ W1s,
               __nv_fp8_e4m3* __restrict__ o0, __nv_fp8_e4m3* __restrict__ o1,
               int K, int N)
{
    const float* W = blockIdx.z ? W1s : W0;
    __nv_fp8_e4m3* o8 = blockIdx.z ? o1 : o0;
    __shared__ float t[32][33];
    int n0 = blockIdx.x*32, k0 = blockIdx.y*32;
    int tx = threadIdx.x, ty = threadIdx.y;
    #pragma unroll
    for (int i = 0; i < 4; i++)
        t[ty + i*8][tx] = W[(size_t)(k0 + ty + i*8)*N + n0 + tx];
    __syncthreads();
    int flat = ty*32 + tx;
    int nl = flat >> 3, k4 = (flat & 7)*4;
    unsigned pk = 0;
    #pragma unroll
    for (int j = 0; j < 4; j++) {
        __nv_fp8_e4m3 v(t[k4+j][nl]);
        pk |= (unsigned)(*(unsigned char*)&v) << (j*8);
    }
    *(unsigned*)&o8[(size_t)(n0 + nl)*K + k0 + k4] = pk;
}
__global__ __launch_bounds__(256)
void wtrans8(const float* __restrict__ W, __nv_fp8_e4m3* __restrict__ o8, int K, int N)
{
    __shared__ float t[32][33];
    int n0 = blockIdx.x*32, k0 = blockIdx.y*32;
    int tx = threadIdx.x, ty = threadIdx.y;
    #pragma unroll
    for (int i = 0; i < 4; i++)
        t[ty + i*8][tx] = W[(size_t)(k0 + ty + i*8)*N + n0 + tx];
    __syncthreads();
    int flat = ty*32 + tx;
    int nl = flat >> 3, k4 = (flat & 7)*4;
    unsigned pk = 0;
    #pragma unroll
    for (int j = 0; j < 4; j++) {
        __nv_fp8_e4m3 v(t[k4+j][nl]);
        pk |= (unsigned)(*(unsigned char*)&v) << (j*8);
    }
    *(unsigned*)&o8[(size_t)(n0 + nl)*K + k0 + k4] = pk;
}

// ---------------- LayerNorm -> bf16 pair ----------------
__global__ __launch_bounds__(256)
void ln_kernel(const float* __restrict__ in, const float* __restrict__ g,
               const float* __restrict__ bcoef,
               __nv_bfloat16* __restrict__ oh, __nv_bfloat16* __restrict__ ol)
{
    int row = blockIdx.x, tid = threadIdx.x;
    float4 v = ((const float4*)(in + (size_t)row*DM))[tid];
    __shared__ float red1[8], red2[8];
    float s = v.x + v.y + v.z + v.w;
    #pragma unroll
    for (int o = 16; o > 0; o >>= 1) s += __shfl_xor_sync(0xffffffffu, s, o);
    if ((tid & 31) == 0) red1[tid >> 5] = s;
    __syncthreads();
    float tot = 0.f;
    #pragma unroll
    for (int i = 0; i < 8; i++) tot += red1[i];
    float mean = tot * (1.0f/DM);
    float dx = v.x-mean, dy = v.y-mean, dz = v.z-mean, dw = v.w-mean;
    float sq = dx*dx + dy*dy + dz*dz + dw*dw;
    #pragma unroll
    for (int o = 16; o > 0; o >>= 1) sq += __shfl_xor_sync(0xffffffffu, sq, o);
    if ((tid & 31) == 0) red2[tid >> 5] = sq;
    __syncthreads();
    float tot2 = 0.f;
    #pragma unroll
    for (int i = 0; i < 8; i++) tot2 += red2[i];
    float rstd = rsqrtf(tot2*(1.0f/DM) + 1e-5f);
    float4 gg = ((const float4*)g)[tid];
    float4 bb = ((const float4*)bcoef)[tid];
    float o0 = dx*rstd*gg.x+bb.x, o1 = dy*rstd*gg.y+bb.y;
    float o2 = dz*rstd*gg.z+bb.z, o3 = dw*rstd*gg.w+bb.w;
    __nv_bfloat16 h0,l0,h1,l1,h2,l2,h3,l3;
    split_bf16(o0,h0,l0); split_bf16(o1,h1,l1); split_bf16(o2,h2,l2); split_bf16(o3,h3,l3);
    __nv_bfloat162* ph = (__nv_bfloat162*)(oh + (size_t)row*DM);
    __nv_bfloat162* pl = (__nv_bfloat162*)(ol + (size_t)row*DM);
    ph[tid*2] = __nv_bfloat162{h0,h1}; ph[tid*2+1] = __nv_bfloat162{h2,h3};
    pl[tid*2] = __nv_bfloat162{l0,l1}; pl[tid*2+1] = __nv_bfloat162{l2,l3};
}

// ---------------- conv -> fp8 only ----------------
__global__ __launch_bounds__(256)
void conv_kernel(const float* __restrict__ xg, const float* __restrict__ cw,
                 const float* __restrict__ cb, __nv_fp8_e4m3* __restrict__ o8)
{
    int idx = blockIdx.x*blockDim.x + threadIdx.x;
    int d = idx & (DI-1);
    int token = idx >> 11;
    int t = token & (SEQ-1);
    float acc = cb[d];
    #pragma unroll
    for (int k = 0; k < 4; k++) {
        int ts = t - 3 + k;
        if (ts >= 0) acc += xg[(size_t)(token-3+k)*(2*DI) + d] * cw[d*4+k];
    }
    o8[idx] = __nv_fp8_e4m3(acc);
}

// ---------------- selective scan -> bf16 pair (simple R12 loop) ----------------
__global__ __launch_bounds__(256)
void scan_kernel(const float* __restrict__ xg, const float* __restrict__ delta,
                 const __nv_bfloat16* __restrict__ Bm, const __nv_bfloat16* __restrict__ Cm,
                 const float* __restrict__ A_log, const float* __restrict__ Dp,
                 __nv_bfloat16* __restrict__ yh, __nv_bfloat16* __restrict__ yl)
{
    int tid = blockIdx.x*blockDim.x + threadIdx.x;
    int n = tid & (DS-1);
    int d = (tid >> 4) & (DI-1);
    int b = tid >> 15;
    float Aneg = -expf(A_log[d*DS + n]);
    float Dval = Dp[d];
    float h = 0.f;
    int base_tok = b*SEQ;
    for (int t = 0; t < SEQ; ++t) {
        int token = base_tok + t;
        float dv = delta[(size_t)token*DI + d];
        float xp = xg[(size_t)token*(2*DI) + d];
        float bm = __bfloat162float(Bm[(size_t)token*(DI*DS) + d*DS + n]);
        float cm = __bfloat162float(Cm[(size_t)token*(DI*DS) + d*DS + n]);
        float a = __expf(dv*Aneg);
        h = a*h + (dv*bm)*xp;
        float yv = cm*h;
        yv += __shfl_xor_sync(0xffffffffu, yv, 1);
        yv += __shfl_xor_sync(0xffffffffu, yv, 2);
        yv += __shfl_xor_sync(0xffffffffu, yv, 4);
        yv += __shfl_xor_sync(0xffffffffu, yv, 8);
        if (n == 0) {
            float g = xg[(size_t)token*(2*DI) + DI + d];
            float sg = g / (1.0f + __expf(-g));
            float val = (yv + Dval*xp)*sg;
            __nv_bfloat16 hh, ll; split_bf16(val, hh, ll);
            yh[(size_t)token*DI + d] = hh;
            yl[(size_t)token*DI + d] = ll;
        }
    }
}

// ---------------- host ----------------
template<int EPI, int OMODE>
static void launch_hgemm(const __nv_bfloat16* Ah, const __nv_bfloat16* Al,
                         const __nv_bfloat16* Bh, const __nv_bfloat16* Bl,
                         int K, int N, const float* bias, const float* add,
                         float* outf, __nv_bfloat16* oh, __nv_bfloat16* ol)
{
    cudaFuncSetAttribute(hgemm<EPI,OMODE>, cudaFuncAttributeMaxDynamicSharedMemorySize, SMEM_B);
    hgemm<EPI,OMODE><<<dim3(MTOK/BM, N/BN), 512, SMEM_B>>>(Ah, Al, Bh, Bl, K, N,
                                                            bias, add, outf, oh, ol);
}
template<int EPI, int OMODE>
static void launch_fgemm(const __nv_fp8_e4m3* A8, const __nv_fp8_e4m3* B8,
                         int K, int N, const float* bias,
                         float* outf, __nv_bfloat16* oh)
{
    cudaFuncSetAttribute(fgemm<EPI,OMODE>, cudaFuncAttributeMaxDynamicSharedMemorySize, F_SMEM);
    fgemm<EPI,OMODE><<<dim3(MTOK/BM, N/FN), 256, F_SMEM>>>(A8, B8, K, N, bias, outf, oh);
}

extern "C" void kernel_launch(void* const* d_in, const int* in_sizes, int n_in,
                              void* d_out, int out_size)
{
    const float* x      = (const float*)d_in[0];
    const float* ln1_g  = (const float*)d_in[1];
    const float* ln1_b  = (const float*)d_in[2];
    const float* W_in   = (const float*)d_in[3];
    const float* b_in   = (const float*)d_in[4];
    const float* conv_w = (const float*)d_in[5];
    const float* conv_b = (const float*)d_in[6];
    const float* A_log  = (const float*)d_in[7];
    const float* W_B    = (const float*)d_in[8];
    const float* b_B    = (const float*)d_in[9];
    const float* W_C    = (const float*)d_in[10];
    const float* b_C    = (const float*)d_in[11];
    const float* Dp     = (const float*)d_in[12];
    const float* W_dt   = (const float*)d_in[13];
    const float* b_dt   = (const float*)d_in[14];
    const float* W_out  = (const float*)d_in[15];
    const float* b_out  = (const float*)d_in[16];
    const float* ln2_g  = (const float*)d_in[17];
    const float* ln2_b  = (const float*)d_in[18];
    const float* W1     = (const float*)d_in[19];
    const float* b1     = (const float*)d_in[20];
    const float* W2     = (const float*)d_in[21];
    const float* b2     = (const float*)d_in[22];
    float* out = (float*)d_out;

    float *xg, *delta, *x2;
    cudaGetSymbolAddress((void**)&xg, g_xg);
    cudaGetSymbolAddress((void**)&delta, g_delta);
    cudaGetSymbolAddress((void**)&x2, g_x2);
    __nv_bfloat16 *Bm, *Cm;
    cudaGetSymbolAddress((void**)&Bm, g_Bm);
    cudaGetSymbolAddress((void**)&Cm, g_Cm);
    __nv_bfloat16 *xnh,*xnl,*yh,*yl,*xn2h,*xn2l,*h1h,*h1l;
    cudaGetSymbolAddress((void**)&xnh, g_xn_h);   cudaGetSymbolAddress((void**)&xnl, g_xn_l);
    cudaGetSymbolAddress((void**)&yh,  g_y_h);    cudaGetSymbolAddress((void**)&yl,  g_y_l);
    cudaGetSymbolAddress((void**)&xn2h,g_xn2_h);  cudaGetSymbolAddress((void**)&xn2l,g_xn2_l);
    cudaGetSymbolAddress((void**)&h1h, g_h1_h);   cudaGetSymbolAddress((void**)&h1l, g_h1_l);
    __nv_fp8_e4m3 *xc8, *WB8, *WC8, *Wdt8;
    cudaGetSymbolAddress((void**)&xc8, g_xc8);
    cudaGetSymbolAddress((void**)&WB8, g_WB8);
    cudaGetSymbolAddress((void**)&WC8, g_WC8);
    cudaGetSymbolAddress((void**)&Wdt8, g_Wdt8);
    __nv_bfloat16 *Winh,*Winl,*Wouth,*Woutl,*W1h,*W1l,*W2h,*W2l;
    cudaGetSymbolAddress((void**)&Winh, g_Win_h); cudaGetSymbolAddress((void**)&Winl, g_Win_l);
    cudaGetSymbolAddress((void**)&Wouth,g_Wout_h);cudaGetSymbolAddress((void**)&Woutl,g_Wout_l);
    cudaGetSymbolAddress((void**)&W1h,  g_W1_h);  cudaGetSymbolAddress((void**)&W1l,  g_W1_l);
    cudaGetSymbolAddress((void**)&W2h,  g_W2_h);  cudaGetSymbolAddress((void**)&W2l,  g_W2_l);

    cudaFuncSetAttribute(fgemm2, cudaFuncAttributeMaxDynamicSharedMemorySize, F_SMEM);

    dim3 tb(32, 8);
    // keep my launch index 3 = hgemm<0,0> (ncu captures it)
    wtrans <<<dim3((2*DI)/32, DM/32),  tb>>>(W_in, Winh, Winl, DM, 2*DI);            // 0
    ln_kernel<<<MTOK, 256>>>(x, ln1_g, ln1_b, xnh, xnl);                             // 1
    wtrans8_2<<<dim3((DI*DS)/32, DI/32, 2), tb>>>(W_B, W_C, WB8, WC8, DI, DI*DS);    // 2
    launch_hgemm<0,0>(xnh, xnl, Winh, Winl, DM, 2*DI, b_in, nullptr, xg, nullptr, nullptr); // 3 <- profiled
    conv_kernel<<<(MTOK*DI)/256, 256>>>(xg, conv_w, conv_b, xc8);                    // 4
    fgemm2<<<dim3(MTOK/BM, (DI*DS)/FN, 2), 256, F_SMEM>>>(xc8, WB8, WC8, DI, DI*DS,
                                                          b_B, b_C, Bm, Cm);         // 5
    wtrans8<<<dim3(DI/32, DI/32),      tb>>>(W_dt, Wdt8, DI, DI);                    // 6
    launch_fgemm<1,0>(xc8, Wdt8, DI, DI, b_dt, delta, nullptr);                      // 7
    scan_kernel<<<256, 256>>>(xg, delta, Bm, Cm, A_log, Dp, yh, yl);                 // 8
    wtrans <<<dim3(DM/32, DI/32),      tb>>>(W_out, Wouth, Woutl, DI, DM);           // 9
    launch_hgemm<3,0>(yh, yl, Wouth, Woutl, DI, DM, b_out, x, x2, nullptr, nullptr); // 10
    ln_kernel<<<MTOK, 256>>>(x2, ln2_g, ln2_b, xn2h, xn2l);                          // 11
    wtrans <<<dim3(DFF/32, DM/32),     tb>>>(W1, W1h, W1l, DM, DFF);                 // 12
    launch_hgemm<2,1>(xn2h, xn2l, W1h, W1l, DM, DFF, b1, nullptr, nullptr, h1h, h1l);// 13
    wtrans <<<dim3(DM/32, DFF/32),     tb>>>(W2, W2h, W2l, DFF, DM);                 // 14
    launch_hgemm<3,0>(h1h, h1l, W2h, W2l, DFF, DM, b2, x2, out, nullptr, nullptr);   // 15
}

// round 16
// speedup vs baseline: 1.1568x; 1.0888x over previous
#include <cuda_runtime.h>
#include <cuda_bf16.h>
#include <cuda_fp8.h>
#include <math.h>

#define B_SZ 2
#define SEQ  1024
#define DM   1024
#define DI   2048
#define DS   16
#define DFF  4096
#define MTOK (B_SZ*SEQ)

// ---- bf16 GEMM tiling: CTA 128x256, 512 thr (4x4 warps), BK=32, 3-stage ----
#define BM 128
#define BN 256
#define BK 32
#define NSTAGE 3
#define ROWB 80
#define A_SPLIT (BM*ROWB)
#define A_BOTH  (2*A_SPLIT)
#define B_SPLIT (BN*ROWB)
#define B_BOTH  (2*B_SPLIT)
#define STAGE_B (A_BOTH + B_BOTH)
#define SMEM_B  (NSTAGE*STAGE_B)

// ---- fp8 GEMM tiling: CTA 128x128, warp 64x32 (2x4), FBK=128, 3-stage, 2 CTA/SM ----
#define FN 128
#define FBK 128
#define FROWB 144
#define F_A (BM*FROWB)
#define F_B (FN*FROWB)
#define F_STAGE (F_A + F_B)
#define F_SMEM (NSTAGE*F_STAGE)

// ---- fp32 scratch ----
__device__ float g_xg   [MTOK*2*DI];
__device__ float g_delta[MTOK*DI];
__device__ float g_x2   [MTOK*DM];
// ---- bf16 Bm/Cm ----
__device__ __nv_bfloat16 g_Bm[67108864];
__device__ __nv_bfloat16 g_Cm[67108864];
// ---- bf16 activation pairs ----
__device__ __nv_bfloat16 g_xn_h [MTOK*DM],  g_xn_l [MTOK*DM];
__device__ __nv_bfloat16 g_y_h  [MTOK*DI],  g_y_l  [MTOK*DI];
__device__ __nv_bfloat16 g_xn2_h[MTOK*DM],  g_xn2_l[MTOK*DM];
__device__ __nv_bfloat16 g_h1_h [MTOK*DFF], g_h1_l [MTOK*DFF];
// ---- fp8 operands ----
__device__ __nv_fp8_e4m3 g_xc8  [MTOK*DI];
__device__ __nv_fp8_e4m3 g_WB8  [DI*DI*DS];
__device__ __nv_fp8_e4m3 g_WC8  [DI*DI*DS];
__device__ __nv_fp8_e4m3 g_Wdt8 [DI*DI];
// ---- bf16 transposed weight pairs [N,K] ----
__device__ __nv_bfloat16 g_Win_h [2*DI*DM],  g_Win_l [2*DI*DM];
__device__ __nv_bfloat16 g_Wout_h[DM*DI],    g_Wout_l[DM*DI];
__device__ __nv_bfloat16 g_W1_h  [DFF*DM],   g_W1_l  [DFF*DM];
__device__ __nv_bfloat16 g_W2_h  [DM*DFF],   g_W2_l  [DM*DFF];

// ---------------- helpers ----------------
__device__ __forceinline__ unsigned s2u(const void* p) {
    unsigned a;
    asm("{ .reg .u64 t; cvta.to.shared.u64 t, %1; cvt.u32.u64 %0, t; }" : "=r"(a) : "l"(p));
    return a;
}
__device__ __forceinline__ void cp16(unsigned d, const void* s) {
    asm volatile("cp.async.cg.shared.global [%0], [%1], 16;" :: "r"(d), "l"(s));
}
#define CP_COMMIT() asm volatile("cp.async.commit_group;" ::: "memory")
#define CP_WAIT1()  asm volatile("cp.async.wait_group 1;" ::: "memory")
#define LDSM4(r, addr) \
    asm volatile("ldmatrix.sync.aligned.m8n8.x4.shared.b16 {%0,%1,%2,%3}, [%4];" \
        : "=r"((r)[0]),"=r"((r)[1]),"=r"((r)[2]),"=r"((r)[3]) : "r"(addr))
#define MMA4(d, a, b0v, b1v) \
    asm volatile("mma.sync.aligned.m16n8k16.row.col.f32.bf16.bf16.f32 " \
        "{%0,%1,%2,%3},{%4,%5,%6,%7},{%8,%9},{%0,%1,%2,%3};" \
        : "+f"((d)[0]),"+f"((d)[1]),"+f"((d)[2]),"+f"((d)[3]) \
        : "r"((a)[0]),"r"((a)[1]),"r"((a)[2]),"r"((a)[3]),"r"(b0v),"r"(b1v))
#define MMA8(d, a, b0v, b1v) \
    asm volatile("mma.sync.aligned.m16n8k32.row.col.f32.e4m3.e4m3.f32 " \
        "{%0,%1,%2,%3},{%4,%5,%6,%7},{%8,%9},{%0,%1,%2,%3};" \
        : "+f"((d)[0]),"+f"((d)[1]),"+f"((d)[2]),"+f"((d)[3]) \
        : "r"((a)[0]),"r"((a)[1]),"r"((a)[2]),"r"((a)[3]),"r"(b0v),"r"(b1v))

__device__ __forceinline__ void split_bf16(float v, __nv_bfloat16& h, __nv_bfloat16& l) {
    h = __float2bfloat16(v);
    l = __float2bfloat16(v - __bfloat162float(h));
}

// ---------------- epilogue helper ----------------
// OMODE: 0 fp32 ; 1 bf16 hi/lo pair ; 2 bf16 single
template<int EPI, int OMODE>
__device__ __forceinline__ void epi2(int r, int c, float v0, float v1, int N,
    const float* __restrict__ bias, const float* __restrict__ add,
    float* __restrict__ outf, __nv_bfloat16* __restrict__ oh, __nv_bfloat16* __restrict__ ol)
{
    size_t go = (size_t)r*N + c;
    float2 bb = *(const float2*)&bias[c];
    v0 += bb.x; v1 += bb.y;
    if (EPI == 3) { float2 aa = *(const float2*)&add[go]; v0 += aa.x; v1 += aa.y; }
    if (EPI == 1) {
        v0 = 1.0f/(1.0f + expf(-v0))*0.099f + 0.001f;
        v1 = 1.0f/(1.0f + expf(-v1))*0.099f + 0.001f;
    }
    if (EPI == 2) {
        v0 = 0.5f*v0*(1.0f + erff(v0*0.70710678118654752f));
        v1 = 0.5f*v1*(1.0f + erff(v1*0.70710678118654752f));
    }
    if (OMODE == 1) {
        __nv_bfloat16 h0,l0,h1,l1;
        split_bf16(v0,h0,l0); split_bf16(v1,h1,l1);
        *(__nv_bfloat162*)&oh[go] = __nv_bfloat162{h0,h1};
        *(__nv_bfloat162*)&ol[go] = __nv_bfloat162{l0,l1};
    } else if (OMODE == 2) {
        *(__nv_bfloat162*)&oh[go] =
            __nv_bfloat162{__float2bfloat16(v0), __float2bfloat16(v1)};
    } else {
        float2 o; o.x = v0; o.y = v1;
        *(float2*)&outf[go] = o;
    }
}

// ---------------- bf16 split HMMA GEMM (3-term), 512 threads, BN=256 ----------------
// KS=true: 2-way split-K (blockIdx.z); output accumulated atomically into zeroed
// fp32 buffer; bias+residual contributed by z==0 only (EPI must be 3, OMODE 0).
template<int EPI, int OMODE, bool KS>
__global__ __launch_bounds__(512, 1)
void hgemm(const __nv_bfloat16* __restrict__ Ah, const __nv_bfloat16* __restrict__ Al,
           const __nv_bfloat16* __restrict__ Bh, const __nv_bfloat16* __restrict__ Bl,
           int K, int N,
           const float* __restrict__ bias, const float* __restrict__ add,
           float* __restrict__ outf,
           __nv_bfloat16* __restrict__ oh, __nv_bfloat16* __restrict__ ol)
{
    extern __shared__ char sm[];
    unsigned sbase = s2u(sm);
    int tid = threadIdx.x, lane = tid & 31, wid = tid >> 5;
    int wm = wid & 3, wn = wid >> 2;             // 4x4 warps; warp tile 32 x 64
    int crow = blockIdx.x * BM, ccol = blockIdx.y * BN;
    int kbase = KS ? blockIdx.z * (K >> 1) : 0;

    bool aact = tid < 256;
    int arow = tid & 127, asp = (tid >> 7) & 1;
    const __nv_bfloat16* Asrc = (asp ? Al : Ah) + (size_t)(crow + arow)*K + kbase;
    unsigned adst = sbase + asp*A_SPLIT + arow*ROWB;
    int brow = tid & 255, bsp = tid >> 8;
    const __nv_bfloat16* Bsrc = (bsp ? Bl : Bh) + (size_t)(ccol + brow)*K + kbase;
    unsigned bdst = sbase + A_BOTH + bsp*B_SPLIT + brow*ROWB;

    float acc[2][8][4];
    #pragma unroll
    for (int i = 0; i < 2; i++)
        #pragma unroll
        for (int j = 0; j < 8; j++)
            #pragma unroll
            for (int q = 0; q < 4; q++) acc[i][j][q] = 0.f;

    const int nk = (KS ? (K >> 1) : K) / BK;

    #pragma unroll
    for (int st = 0; st < NSTAGE-1; st++) {
        unsigned so = st*STAGE_B;
        #pragma unroll
        for (int c = 0; c < 4; c++) {
            if (aact) cp16(adst + so + c*16, Asrc + st*BK + c*8);
            cp16(bdst + so + c*16, Bsrc + st*BK + c*8);
        }
        CP_COMMIT();
    }

    int rrow = lane & 15, rhalf = lane >> 4;

    for (int i = 0; i < nk; i++) {
        CP_WAIT1();
        __syncthreads();

        int j = i + NSTAGE - 1;
        if (j < nk) {
            unsigned so = (j % NSTAGE)*STAGE_B;
            #pragma unroll
            for (int c = 0; c < 4; c++) {
                if (aact) cp16(adst + so + c*16, Asrc + j*BK + c*8);
                cp16(bdst + so + c*16, Bsrc + j*BK + c*8);
            }
        }
        CP_COMMIT();

        unsigned aST = sbase + (i % NSTAGE)*STAGE_B;
        unsigned bST = aST + A_BOTH;

        #pragma unroll
        for (int ks = 0; ks < 2; ks++) {
            int koff = ks*16;
            unsigned ah[2][4], al_[2][4];
            #pragma unroll
            for (int mt = 0; mt < 2; mt++) {
                unsigned base = aST + (unsigned)(wm*32 + mt*16 + rrow)*ROWB
                              + (unsigned)(koff + rhalf*8)*2;
                LDSM4(ah[mt], base);
                LDSM4(al_[mt], base + A_SPLIT);
            }
            #pragma unroll
            for (int p = 0; p < 4; p++) {
                unsigned base = bST + (unsigned)(wn*64 + p*16 + rrow)*ROWB
                              + (unsigned)(koff + rhalf*8)*2;
                unsigned th[4], tl[4];
                LDSM4(th, base);
                LDSM4(tl, base + B_SPLIT);
                #pragma unroll
                for (int mt = 0; mt < 2; mt++) {
                    MMA4(acc[mt][2*p],   ah[mt],  th[0], th[2]);
                    MMA4(acc[mt][2*p+1], ah[mt],  th[1], th[3]);
                    MMA4(acc[mt][2*p],   ah[mt],  tl[0], tl[2]);
                    MMA4(acc[mt][2*p+1], ah[mt],  tl[1], tl[3]);
                    MMA4(acc[mt][2*p],   al_[mt], th[0], th[2]);
                    MMA4(acc[mt][2*p+1], al_[mt], th[1], th[3]);
                }
            }
        }
    }

    #pragma unroll
    for (int mt = 0; mt < 2; mt++) {
        int r0 = crow + wm*32 + mt*16 + (lane >> 2);
        #pragma unroll
        for (int nt = 0; nt < 8; nt++) {
            int c = ccol + wn*64 + nt*8 + 2*(lane & 3);
            if (KS) {
                #pragma unroll
                for (int half = 0; half < 2; half++) {
                    int r = r0 + half*8;
                    size_t go = (size_t)r*N + c;
                    float v0 = acc[mt][nt][2*half], v1 = acc[mt][nt][2*half+1];
                    if (blockIdx.z == 0) {
                        float2 bb = *(const float2*)&bias[c];
                        float2 aa = *(const float2*)&add[go];
                        v0 += bb.x + aa.x; v1 += bb.y + aa.y;
                    }
                    atomicAdd(&outf[go],   v0);
                    atomicAdd(&outf[go+1], v1);
                }
            } else {
                epi2<EPI,OMODE>(r0,     c, acc[mt][nt][0], acc[mt][nt][1], N, bias, add, outf, oh, ol);
                epi2<EPI,OMODE>(r0 + 8, c, acc[mt][nt][2], acc[mt][nt][3], N, bias, add, outf, oh, ol);
            }
        }
    }
}

// ---------------- fp8 e4m3 GEMM core ----------------
template<int EPI, int OMODE>
__device__ __forceinline__ void fgemm_body(
    const __nv_fp8_e4m3* __restrict__ A8, const __nv_fp8_e4m3* __restrict__ B8,
    int K, int N, const float* __restrict__ bias,
    float* __restrict__ outf, __nv_bfloat16* __restrict__ oh, char* sm)
{
    unsigned sbase = s2u(sm);
    int tid = threadIdx.x, lane = tid & 31, wid = tid >> 5;
    int wm = wid & 1, wn = wid >> 1;            // 2x4 warps; warp tile 64 x 32
    int crow = blockIdx.x * BM, ccol = blockIdx.y * FN;

    int r2 = tid >> 1, hf = tid & 1;
    const char* Asrc = (const char*)(A8 + (size_t)(crow + r2)*K) + hf*64;
    const char* Bsrc = (const char*)(B8 + (size_t)(ccol + r2)*K) + hf*64;
    unsigned adst = sbase + r2*FROWB + hf*64;
    unsigned bdst = sbase + F_A + r2*FROWB + hf*64;

    float acc[4][4][4];
    #pragma unroll
    for (int i = 0; i < 4; i++)
        #pragma unroll
        for (int j = 0; j < 4; j++)
            #pragma unroll
            for (int q = 0; q < 4; q++) acc[i][j][q] = 0.f;

    const int nk = K / FBK;

    #pragma unroll
    for (int st = 0; st < NSTAGE-1; st++) {
        unsigned so = st*F_STAGE;
        #pragma unroll
        for (int c = 0; c < 4; c++) {
            cp16(adst + so + c*16, Asrc + st*FBK + c*16);
            cp16(bdst + so + c*16, Bsrc + st*FBK + c*16);
        }
        CP_COMMIT();
    }

    int rrow = lane & 15, rhalf = lane >> 4;

    for (int i = 0; i < nk; i++) {
        CP_WAIT1();
        __syncthreads();

        int j = i + NSTAGE - 1;
        if (j < nk) {
            unsigned so = (j % NSTAGE)*F_STAGE;
            #pragma unroll
            for (int c = 0; c < 4; c++) {
                cp16(adst + so + c*16, Asrc + j*FBK + c*16);
                cp16(bdst + so + c*16, Bsrc + j*FBK + c*16);
            }
        }
        CP_COMMIT();

        unsigned aST = sbase + (i % NSTAGE)*F_STAGE;
        unsigned bST = aST + F_A;

        #pragma unroll
        for (int ks = 0; ks < 4; ks++) {
            int koff = ks*32;
            unsigned av[4][4];
            #pragma unroll
            for (int mt = 0; mt < 4; mt++) {
                unsigned base = aST + (unsigned)(wm*64 + mt*16 + rrow)*FROWB
                              + (unsigned)(koff + rhalf*16);
                LDSM4(av[mt], base);
            }
            #pragma unroll
            for (int p = 0; p < 2; p++) {
                unsigned base = bST + (unsigned)(wn*32 + p*16 + rrow)*FROWB
                              + (unsigned)(koff + rhalf*16);
                unsigned tb[4];
                LDSM4(tb, base);
                #pragma unroll
                for (int mt = 0; mt < 4; mt++) {
                    MMA8(acc[mt][2*p],   av[mt], tb[0], tb[2]);
                    MMA8(acc[mt][2*p+1], av[mt], tb[1], tb[3]);
                }
            }
        }
    }

    #pragma unroll
    for (int mt = 0; mt < 4; mt++) {
        int r0 = crow + wm*64 + mt*16 + (lane >> 2);
        #pragma unroll
        for (int nt = 0; nt < 4; nt++) {
            int c = ccol + wn*32 + nt*8 + 2*(lane & 3);
            epi2<EPI,OMODE>(r0,     c, acc[mt][nt][0], acc[mt][nt][1], N, bias, nullptr, outf, oh, nullptr);
            epi2<EPI,OMODE>(r0 + 8, c, acc[mt][nt][2], acc[mt][nt][3], N, bias, nullptr, outf, oh, nullptr);
        }
    }
}

template<int EPI, int OMODE>
__global__ __launch_bounds__(256, 2)
void fgemm(const __nv_fp8_e4m3* __restrict__ A8, const __nv_fp8_e4m3* __restrict__ B8,
           int K, int N, const float* __restrict__ bias,
           float* __restrict__ outf, __nv_bfloat16* __restrict__ oh)
{
    extern __shared__ char sm[];
    fgemm_body<EPI,OMODE>(A8, B8, K, N, bias, outf, oh, sm);
}

__global__ __launch_bounds__(256, 2)
void fgemm2(const __nv_fp8_e4m3* __restrict__ A8,
            const __nv_fp8_e4m3* __restrict__ B0, const __nv_fp8_e4m3* __restrict__ B1,
            int K, int N, const float* __restrict__ bias0, const float* __restrict__ bias1,
            __nv_bfloat16* __restrict__ o0, __nv_bfloat16* __restrict__ o1)
{
    extern __shared__ char sm[];
    const __nv_fp8_e4m3* B8 = blockIdx.z ? B1 : B0;
    const float* bias = blockIdx.z ? bias1 : bias0;
    __nv_bfloat16* oh = blockIdx.z ? o1 : o0;
    fgemm_body<0,2>(A8, B8, K, N, bias, nullptr, oh, sm);
}

// ---------------- weight transpose kernels ----------------
__global__ __launch_bounds__(256)
void wtrans(const float* __restrict__ W, __nv_bfloat16* __restrict__ hi,
            __nv_bfloat16* __restrict__ lo, int K, int N)
{
    __shared__ float t[32][33];
    int n0 = blockIdx.x*32, k0 = blockIdx.y*32;
    int tx = threadIdx.x, ty = threadIdx.y;
    #pragma unroll
    for (int i = 0; i < 4; i++)
        t[ty + i*8][tx] = W[(size_t)(k0 + ty + i*8)*N + n0 + tx];
    __syncthreads();
    int flat = ty*32 + tx;
    int nl = flat >> 3, k4 = (flat & 7)*4;
    __nv_bfloat16 h[4], l[4];
    #pragma unroll
    for (int j = 0; j < 4; j++) split_bf16(t[k4+j][nl], h[j], l[j]);
    size_t o = (size_t)(n0 + nl)*K + k0 + k4;
    uint2 ph, pl;
    ph.x = ((unsigned)__bfloat16_as_ushort(h[1]) << 16) | __bfloat16_as_ushort(h[0]);
    ph.y = ((unsigned)__bfloat16_as_ushort(h[3]) << 16) | __bfloat16_as_ushort(h[2]);
    pl.x = ((unsigned)__bfloat16_as_ushort(l[1]) << 16) | __bfloat16_as_ushort(l[0]);
    pl.y = ((unsigned)__bfloat16_as_ushort(l[3]) << 16) | __bfloat16_as_ushort(l[2]);
    *(uint2*)&hi[o] = ph;
    *(uint2*)&lo[o] = pl;
}
__global__ __launch_bounds__(256)
void wtrans8_2(const float* __restrict__ W0, const float* __restrict__ W1s,
               __nv_fp8_e4m3* __restrict__ o0, __nv_fp8_e4m3* __restrict__ o1,
               int K, int N)
{
    const float* W = blockIdx.z ? W1s : W0;
    __nv_fp8_e4m3* o8 = blockIdx.z ? o1 : o0;
    __shared__ float t[32][33];
    int n0 = blockIdx.x*32, k0 = blockIdx.y*32;
    int tx = threadIdx.x, ty = threadIdx.y;
    #pragma unroll
    for (int i = 0; i < 4; i++)
        t[ty + i*8][tx] = W[(size_t)(k0 + ty + i*8)*N + n0 + tx];
    __syncthreads();
    int flat = ty*32 + tx;
    int nl = flat >> 3, k4 = (flat & 7)*4;
    unsigned pk = 0;
    #pragma unroll
    for (int j = 0; j < 4; j++) {
        __nv_fp8_e4m3 v(t[k4+j][nl]);
        pk |= (unsigned)(*(unsigned char*)&v) << (j*8);
    }
    *(unsigned*)&o8[(size_t)(n0 + nl)*K + k0 + k4] = pk;
}
__global__ __launch_bounds__(256)
void wtrans8(const float* __restrict__ W, __nv_fp8_e4m3* __restrict__ o8, int K, int N)
{
    __shared__ float t[32][33];
    int n0 = blockIdx.x*32, k0 = blockIdx.y*32;
    int tx = threadIdx.x, ty = threadIdx.y;
    #pragma unroll
    for (int i = 0; i < 4; i++)
        t[ty + i*8][tx] = W[(size_t)(k0 + ty + i*8)*N + n0 + tx];
    __syncthreads();
    int flat = ty*32 + tx;
    int nl = flat >> 3, k4 = (flat & 7)*4;
    unsigned pk = 0;
    #pragma unroll
    for (int j = 0; j < 4; j++) {
        __nv_fp8_e4m3 v(t[k4+j][nl]);
        pk |= (unsigned)(*(unsigned char*)&v) << (j*8);
    }
    *(unsigned*)&o8[(size_t)(n0 + nl)*K + k0 + k4] = pk;
}

// ---------------- LayerNorm -> bf16 pair ----------------
__global__ __launch_bounds__(256)
void ln_kernel(const float* __restrict__ in, const float* __restrict__ g,
               const float* __restrict__ bcoef,
               __nv_bfloat16* __restrict__ oh, __nv_bfloat16* __restrict__ ol)
{
    int row = blockIdx.x, tid = threadIdx.x;
    float4 v = ((const float4*)(in + (size_t)row*DM))[tid];
    __shared__ float red1[8], red2[8];
    float s = v.x + v.y + v.z + v.w;
    #pragma unroll
    for (int o = 16; o > 0; o >>= 1) s += __shfl_xor_sync(0xffffffffu, s, o);
    if ((tid & 31) == 0) red1[tid >> 5] = s;
    __syncthreads();
    float tot = 0.f;
    #pragma unroll
    for (int i = 0; i < 8; i++) tot += red1[i];
    float mean = tot * (1.0f/DM);
    float dx = v.x-mean, dy = v.y-mean, dz = v.z-mean, dw = v.w-mean;
    float sq = dx*dx + dy*dy + dz*dz + dw*dw;
    #pragma unroll
    for (int o = 16; o > 0; o >>= 1) sq += __shfl_xor_sync(0xffffffffu, sq, o);
    if ((tid & 31) == 0) red2[tid >> 5] = sq;
    __syncthreads();
    float tot2 = 0.f;
    #pragma unroll
    for (int i = 0; i < 8; i++) tot2 += red2[i];
    float rstd = rsqrtf(tot2*(1.0f/DM) + 1e-5f);
    float4 gg = ((const float4*)g)[tid];
    float4 bb = ((const float4*)bcoef)[tid];
    float o0 = dx*rstd*gg.x+bb.x, o1 = dy*rstd*gg.y+bb.y;
    float o2 = dz*rstd*gg.z+bb.z, o3 = dw*rstd*gg.w+bb.w;
    __nv_bfloat16 h0,l0,h1,l1,h2,l2,h3,l3;
    split_bf16(o0,h0,l0); split_bf16(o1,h1,l1); split_bf16(o2,h2,l2); split_bf16(o3,h3,l3);
    __nv_bfloat162* ph = (__nv_bfloat162*)(oh + (size_t)row*DM);
    __nv_bfloat162* pl = (__nv_bfloat162*)(ol + (size_t)row*DM);
    ph[tid*2] = __nv_bfloat162{h0,h1}; ph[tid*2+1] = __nv_bfloat162{h2,h3};
    pl[tid*2] = __nv_bfloat162{l0,l1}; pl[tid*2+1] = __nv_bfloat162{l2,l3};
}

// ---------------- conv -> fp8 only ----------------
__global__ __launch_bounds__(256)
void conv_kernel(const float* __restrict__ xg, const float* __restrict__ cw,
                 const float* __restrict__ cb, __nv_fp8_e4m3* __restrict__ o8)
{
    int idx = blockIdx.x*blockDim.x + threadIdx.x;
    int d = idx & (DI-1);
    int token = idx >> 11;
    int t = token & (SEQ-1);
    float acc = cb[d];
    #pragma unroll
    for (int k = 0; k < 4; k++) {
        int ts = t - 3 + k;
        if (ts >= 0) acc += xg[(size_t)(token-3+k)*(2*DI) + d] * cw[d*4+k];
    }
    o8[idx] = __nv_fp8_e4m3(acc);
}

// ---------------- selective scan -> bf16 pair ----------------
__global__ __launch_bounds__(256)
void scan_kernel(const float* __restrict__ xg, const float* __restrict__ delta,
                 const __nv_bfloat16* __restrict__ Bm, const __nv_bfloat16* __restrict__ Cm,
                 const float* __restrict__ A_log, const float* __restrict__ Dp,
                 __nv_bfloat16* __restrict__ yh, __nv_bfloat16* __restrict__ yl)
{
    int tid = blockIdx.x*blockDim.x + threadIdx.x;
    int n = tid & (DS-1);
    int d = (tid >> 4) & (DI-1);
    int b = tid >> 15;
    float Aneg = -expf(A_log[d*DS + n]);
    float Dval = Dp[d];
    float h = 0.f;
    int base_tok = b*SEQ;
    for (int t = 0; t < SEQ; ++t) {
        int token = base_tok + t;
        float dv = delta[(size_t)token*DI + d];
        float xp = xg[(size_t)token*(2*DI) + d];
        float bm = __bfloat162float(Bm[(size_t)token*(DI*DS) + d*DS + n]);
        float cm = __bfloat162float(Cm[(size_t)token*(DI*DS) + d*DS + n]);
        float a = __expf(dv*Aneg);
        h = a*h + (dv*bm)*xp;
        float yv = cm*h;
        yv += __shfl_xor_sync(0xffffffffu, yv, 1);
        yv += __shfl_xor_sync(0xffffffffu, yv, 2);
        yv += __shfl_xor_sync(0xffffffffu, yv, 4);
        yv += __shfl_xor_sync(0xffffffffu, yv, 8);
        if (n == 0) {
            float g = xg[(size_t)token*(2*DI) + DI + d];
            float sg = g / (1.0f + __expf(-g));
            float val = (yv + Dval*xp)*sg;
            __nv_bfloat16 hh, ll; split_bf16(val, hh, ll);
            yh[(size_t)token*DI + d] = hh;
            yl[(size_t)token*DI + d] = ll;
        }
    }
}

// ---------------- host ----------------
template<int EPI, int OMODE>
static void launch_hgemm(const __nv_bfloat16* Ah, const __nv_bfloat16* Al,
                         const __nv_bfloat16* Bh, const __nv_bfloat16* Bl,
                         int K, int N, const float* bias, const float* add,
                         float* outf, __nv_bfloat16* oh, __nv_bfloat16* ol)
{
    cudaFuncSetAttribute(hgemm<EPI,OMODE,false>, cudaFuncAttributeMaxDynamicSharedMemorySize, SMEM_B);
    hgemm<EPI,OMODE,false><<<dim3(MTOK/BM, N/BN), 512, SMEM_B>>>(Ah, Al, Bh, Bl, K, N,
                                                                  bias, add, outf, oh, ol);
}
static void launch_hgemm_ks(const __nv_bfloat16* Ah, const __nv_bfloat16* Al,
                            const __nv_bfloat16* Bh, const __nv_bfloat16* Bl,
                            int K, int N, const float* bias, const float* add,
                            float* outf)
{
    cudaFuncSetAttribute(hgemm<3,0,true>, cudaFuncAttributeMaxDynamicSharedMemorySize, SMEM_B);
    hgemm<3,0,true><<<dim3(MTOK/BM, N/BN, 2), 512, SMEM_B>>>(Ah, Al, Bh, Bl, K, N,
                                                              bias, add, outf, nullptr, nullptr);
}
template<int EPI, int OMODE>
static void launch_fgemm(const __nv_fp8_e4m3* A8, const __nv_fp8_e4m3* B8,
                         int K, int N, const float* bias,
                         float* outf, __nv_bfloat16* oh)
{
    cudaFuncSetAttribute(fgemm<EPI,OMODE>, cudaFuncAttributeMaxDynamicSharedMemorySize, F_SMEM);
    fgemm<EPI,OMODE><<<dim3(MTOK/BM, N/FN), 256, F_SMEM>>>(A8, B8, K, N, bias, outf, oh);
}

extern "C" void kernel_launch(void* const* d_in, const int* in_sizes, int n_in,
                              void* d_out, int out_size)
{
    const float* x      = (const float*)d_in[0];
    const float* ln1_g  = (const float*)d_in[1];
    const float* ln1_b  = (const float*)d_in[2];
    const float* W_in   = (const float*)d_in[3];
    const float* b_in   = (const float*)d_in[4];
    const float* conv_w = (const float*)d_in[5];
    const float* conv_b = (const float*)d_in[6];
    const float* A_log  = (const float*)d_in[7];
    const float* W_B    = (const float*)d_in[8];
    const float* b_B    = (const float*)d_in[9];
    const float* W_C    = (const float*)d_in[10];
    const float* b_C    = (const float*)d_in[11];
    const float* Dp     = (const float*)d_in[12];
    const float* W_dt   = (const float*)d_in[13];
    const float* b_dt   = (const float*)d_in[14];
    const float* W_out  = (const float*)d_in[15];
    const float* b_out  = (const float*)d_in[16];
    const float* ln2_g  = (const float*)d_in[17];
    const float* ln2_b  = (const float*)d_in[18];
    const float* W1     = (const float*)d_in[19];
    const float* b1     = (const float*)d_in[20];
    const float* W2     = (const float*)d_in[21];
    const float* b2     = (const float*)d_in[22];
    float* out = (float*)d_out;

    float *xg, *delta, *x2;
    cudaGetSymbolAddress((void**)&xg, g_xg);
    cudaGetSymbolAddress((void**)&delta, g_delta);
    cudaGetSymbolAddress((void**)&x2, g_x2);
    __nv_bfloat16 *Bm, *Cm;
    cudaGetSymbolAddress((void**)&Bm, g_Bm);
    cudaGetSymbolAddress((void**)&Cm, g_Cm);
    __nv_bfloat16 *xnh,*xnl,*yh,*yl,*xn2h,*xn2l,*h1h,*h1l;
    cudaGetSymbolAddress((void**)&xnh, g_xn_h);   cudaGetSymbolAddress((void**)&xnl, g_xn_l);
    cudaGetSymbolAddress((void**)&yh,  g_y_h);    cudaGetSymbolAddress((void**)&yl,  g_y_l);
    cudaGetSymbolAddress((void**)&xn2h,g_xn2_h);  cudaGetSymbolAddress((void**)&xn2l,g_xn2_l);
    cudaGetSymbolAddress((void**)&h1h, g_h1_h);   cudaGetSymbolAddress((void**)&h1l, g_h1_l);
    __nv_fp8_e4m3 *xc8, *WB8, *WC8, *Wdt8;
    cudaGetSymbolAddress((void**)&xc8, g_xc8);
    cudaGetSymbolAddress((void**)&WB8, g_WB8);
    cudaGetSymbolAddress((void**)&WC8, g_WC8);
    cudaGetSymbolAddress((void**)&Wdt8, g_Wdt8);
    __nv_bfloat16 *Winh,*Winl,*Wouth,*Woutl,*W1h,*W1l,*W2h,*W2l;
    cudaGetSymbolAddress((void**)&Winh, g_Win_h); cudaGetSymbolAddress((void**)&Winl, g_Win_l);
    cudaGetSymbolAddress((void**)&Wouth,g_Wout_h);cudaGetSymbolAddress((void**)&Woutl,g_Wout_l);
    cudaGetSymbolAddress((void**)&W1h,  g_W1_h);  cudaGetSymbolAddress((void**)&W1l,  g_W1_l);
    cudaGetSymbolAddress((void**)&W2h,  g_W2_h);  cudaGetSymbolAddress((void**)&W2l,  g_W2_l);

    cudaFuncSetAttribute(fgemm2, cudaFuncAttributeMaxDynamicSharedMemorySize, F_SMEM);

    dim3 tb(32, 8);
    // keep my launch index 3 = hgemm<0,0,false> (ncu captures it)
    wtrans <<<dim3((2*DI)/32, DM/32),  tb>>>(W_in, Winh, Winl, DM, 2*DI);            // 0
    ln_kernel<<<MTOK, 256>>>(x, ln1_g, ln1_b, xnh, xnl);                             // 1
    wtrans8_2<<<dim3((DI*DS)/32, DI/32, 2), tb>>>(W_B, W_C, WB8, WC8, DI, DI*DS);    // 2
    launch_hgemm<0,0>(xnh, xnl, Winh, Winl, DM, 2*DI, b_in, nullptr, xg, nullptr, nullptr); // 3 <- profiled
    conv_kernel<<<(MTOK*DI)/256, 256>>>(xg, conv_w, conv_b, xc8);                    // 4
    fgemm2<<<dim3(MTOK/BM, (DI*DS)/FN, 2), 256, F_SMEM>>>(xc8, WB8, WC8, DI, DI*DS,
                                                          b_B, b_C, Bm, Cm);         // 5
    wtrans8<<<dim3(DI/32, DI/32),      tb>>>(W_dt, Wdt8, DI, DI);                    // 6
    launch_fgemm<1,0>(xc8, Wdt8, DI, DI, b_dt, delta, nullptr);                      // 7
    scan_kernel<<<256, 256>>>(xg, delta, Bm, Cm, A_log, Dp, yh, yl);                 // 8
    wtrans <<<dim3(DM/32, DI/32),      tb>>>(W_out, Wouth, Woutl, DI, DM);           // 9
    cudaMemsetAsync(x2, 0, (size_t)MTOK*DM*sizeof(float));                           // 10
    launch_hgemm_ks(yh, yl, Wouth, Woutl, DI, DM, b_out, x, x2);                     // 11 split-K
    ln_kernel<<<MTOK, 256>>>(x2, ln2_g, ln2_b, xn2h, xn2l);                          // 12
    wtrans <<<dim3(DFF/32, DM/32),     tb>>>(W1, W1h, W1l, DM, DFF);                 // 13
    launch_hgemm<2,1>(xn2h, xn2l, W1h, W1l, DM, DFF, b1, nullptr, nullptr, h1h, h1l);// 14
    wtrans <<<dim3(DM/32, DFF/32),     tb>>>(W2, W2h, W2l, DFF, DM);                 // 15
    cudaMemsetAsync(out, 0, (size_t)MTOK*DM*sizeof(float));                          // 16
    launch_hgemm_ks(h1h, h1l, W2h, W2l, DFF, DM, b2, x2, out);                       // 17 split-K
}